// round 7
// baseline (speedup 1.0000x reference)
#include <cuda_runtime.h>
#include <cuda_bf16.h>
#include <math.h>
#include <stdint.h>

// ---------------- problem constants ----------------
#define BB   4
#define NN   2048
#define DD   768
#define HH   12
#define HDIM 64
#define RS   2304
#define MM   8192
#define KK   768
#define LOG2E 1.4426950408889634f

// ---------------- scratch ----------------
__device__ uint32_t g_q [(size_t)BB * HH * NN * HDIM];   // tf32, scaled
__device__ uint32_t g_k [(size_t)BB * HH * NN * HDIM];   // tf32
__device__ uint32_t g_vT[(size_t)BB * HH * HDIM * NN];   // tf32, transposed
__device__ __nv_bfloat16 g_zh[(size_t)MM * DD],  g_zl[(size_t)MM * DD];
__device__ __nv_bfloat16 g_ah[(size_t)MM * DD],  g_al[(size_t)MM * DD];
__device__ __nv_bfloat16 g_wqh[(size_t)RS * DD], g_wql[(size_t)RS * DD];
__device__ __nv_bfloat16 g_wmh[(size_t)DD * DD], g_wml[(size_t)DD * DD];

// ---------------- helpers ----------------
__device__ __forceinline__ uint32_t smem_u32(const void* p) {
    uint32_t a;
    asm("{ .reg .u64 t; cvta.to.shared.u64 t, %1; cvt.u32.u64 %0, t; }"
        : "=r"(a) : "l"(p));
    return a;
}
__device__ __forceinline__ void mma_bf16(float* c, const uint32_t* a, const uint32_t* b) {
    asm volatile("mma.sync.aligned.m16n8k16.row.col.f32.bf16.bf16.f32 "
        "{%0,%1,%2,%3}, {%4,%5,%6,%7}, {%8,%9}, {%0,%1,%2,%3};"
        : "+f"(c[0]), "+f"(c[1]), "+f"(c[2]), "+f"(c[3])
        : "r"(a[0]), "r"(a[1]), "r"(a[2]), "r"(a[3]), "r"(b[0]), "r"(b[1]));
}
__device__ __forceinline__ void mma_tf32(float* c, const uint32_t* a, uint32_t b0, uint32_t b1) {
    asm volatile("mma.sync.aligned.m16n8k8.row.col.f32.tf32.tf32.f32 "
        "{%0,%1,%2,%3}, {%4,%5,%6,%7}, {%8,%9}, {%0,%1,%2,%3};"
        : "+f"(c[0]), "+f"(c[1]), "+f"(c[2]), "+f"(c[3])
        : "r"(a[0]), "r"(a[1]), "r"(a[2]), "r"(a[3]), "r"(b0), "r"(b1));
}
__device__ __forceinline__ void ldsm4(uint32_t* r, uint32_t a) {
    asm volatile("ldmatrix.sync.aligned.m8n8.x4.shared.b16 {%0,%1,%2,%3}, [%4];"
        : "=r"(r[0]), "=r"(r[1]), "=r"(r[2]), "=r"(r[3]) : "r"(a));
}
__device__ __forceinline__ void cp16(uint32_t d, const void* s) {
    asm volatile("cp.async.cg.shared.global [%0], [%1], 16;" :: "r"(d), "l"(s));
}
#define CP_COMMIT() asm volatile("cp.async.commit_group;" ::: "memory")
#define CP_WAIT0()  asm volatile("cp.async.wait_group 0;" ::: "memory")
#define CP_WAIT1()  asm volatile("cp.async.wait_group 1;" ::: "memory")

__device__ __forceinline__ uint32_t f2tf32(float x) {
    uint32_t r;
    asm("cvt.rna.tf32.f32 %0, %1;" : "=r"(r) : "f"(x));
    return r;
}
__device__ __forceinline__ float ex2(float x) {
    float y;
    asm("ex2.approx.f32 %0, %1;" : "=f"(y) : "f"(x));
    return y;
}

// ============================================================================
// Split pass (all three tensors in one launch): fp32 -> (hi, lo) bf16
// ============================================================================
#define N4_Z  (MM * DD / 4)
#define N4_WQ (RS * DD / 4)
#define N4_WM (DD * DD / 4)

__global__ __launch_bounds__(256) void split_all(
    const float* __restrict__ z, const float* __restrict__ wq,
    const float* __restrict__ wm)
{
    int i = blockIdx.x * blockDim.x + threadIdx.x;
    const float* src;
    __nv_bfloat16 *hi, *lo;
    if (i < N4_Z)                { src = z;  hi = g_zh;  lo = g_zl; }
    else if (i < N4_Z + N4_WQ)   { src = wq; hi = g_wqh; lo = g_wql; i -= N4_Z; }
    else if (i < N4_Z + N4_WQ + N4_WM) { src = wm; hi = g_wmh; lo = g_wml; i -= N4_Z + N4_WQ; }
    else return;
    float4 v = ((const float4*)src)[i];
    __nv_bfloat162 h0 = __floats2bfloat162_rn(v.x, v.y);
    __nv_bfloat162 h1 = __floats2bfloat162_rn(v.z, v.w);
    __nv_bfloat162 l0 = __floats2bfloat162_rn(v.x - __bfloat162float(h0.x),
                                              v.y - __bfloat162float(h0.y));
    __nv_bfloat162 l1 = __floats2bfloat162_rn(v.z - __bfloat162float(h1.x),
                                              v.w - __bfloat162float(h1.y));
    uint2 hp, lp;
    hp.x = *(uint32_t*)&h0; hp.y = *(uint32_t*)&h1;
    lp.x = *(uint32_t*)&l0; lp.y = *(uint32_t*)&l1;
    ((uint2*)hi)[i] = hp;
    ((uint2*)lo)[i] = lp;
}

// ============================================================================
// GEMM (pre-split bf16): 128x128 tile, BK=32, cp.async 2-buf, ldmatrix.
// ============================================================================
#define G_AH 0
#define G_AL 10240
#define G_BH 20480
#define G_BL 30720
#define G_BUF 40960
#define G_SMEM 81920

__global__ __launch_bounds__(256, 2) void gemm_tc(
    const __nv_bfloat16* __restrict__ Ah, const __nv_bfloat16* __restrict__ Al,
    const __nv_bfloat16* __restrict__ Bh, const __nv_bfloat16* __restrict__ Bl,
    const float* __restrict__ bias, float* __restrict__ C, int Nc, int mode)
{
    extern __shared__ char sm[];
    uint32_t sb = smem_u32(sm);
    const int tid = threadIdx.x, wid = tid >> 5, lane = tid & 31;
    const int g = lane >> 2, t = lane & 3;
    const int wm = wid >> 2, wn = wid & 3;
    const int row0 = blockIdx.y * 128, col0 = blockIdx.x * 128;

    const int sr = tid >> 2, sg = tid & 3;
    const size_t gaoff1 = (size_t)(row0 + sr) * KK + sg * 8;
    const size_t gaoff2 = (size_t)(row0 + sr + 64) * KK + sg * 8;
    const size_t gboff1 = (size_t)(col0 + sr) * KK + sg * 8;
    const size_t gboff2 = (size_t)(col0 + sr + 64) * KK + sg * 8;
    const uint32_t so1 = sr * 80 + sg * 16, so2 = (sr + 64) * 80 + sg * 16;

    const uint32_t loA = (uint32_t)(((lane & 7) + ((lane >> 3) & 1) * 8) * 80 + (lane >> 4) * 16);
    const uint32_t loB = (uint32_t)(((lane & 7) + (lane >> 4) * 8) * 80 + ((lane >> 3) & 1) * 16);

    float acc[4][4][4];
    #pragma unroll
    for (int mt = 0; mt < 4; mt++)
        #pragma unroll
        for (int nt = 0; nt < 4; nt++)
            #pragma unroll
            for (int j = 0; j < 4; j++) acc[mt][nt][j] = 0.f;

    {
        uint32_t d = sb;
        cp16(d + G_AH + so1, Ah + gaoff1); cp16(d + G_AH + so2, Ah + gaoff2);
        cp16(d + G_AL + so1, Al + gaoff1); cp16(d + G_AL + so2, Al + gaoff2);
        cp16(d + G_BH + so1, Bh + gboff1); cp16(d + G_BH + so2, Bh + gboff2);
        cp16(d + G_BL + so1, Bl + gboff1); cp16(d + G_BL + so2, Bl + gboff2);
        CP_COMMIT();
    }

    for (int i = 0; i < KK / 32; i++) {
        CP_WAIT0();
        __syncthreads();
        if (i + 1 < KK / 32) {
            const int ke = (i + 1) * 32;
            uint32_t d = sb + ((i + 1) & 1) * G_BUF;
            cp16(d + G_AH + so1, Ah + gaoff1 + ke); cp16(d + G_AH + so2, Ah + gaoff2 + ke);
            cp16(d + G_AL + so1, Al + gaoff1 + ke); cp16(d + G_AL + so2, Al + gaoff2 + ke);
            cp16(d + G_BH + so1, Bh + gboff1 + ke); cp16(d + G_BH + so2, Bh + gboff2 + ke);
            cp16(d + G_BL + so1, Bl + gboff1 + ke); cp16(d + G_BL + so2, Bl + gboff2 + ke);
            CP_COMMIT();
        }
        const uint32_t ab = sb + (i & 1) * G_BUF;
        #pragma unroll
        for (int ks = 0; ks < 2; ks++) {
            uint32_t fah[4][4], fal[4][4], fbh[2][4], fbl[2][4];
            #pragma unroll
            for (int mt = 0; mt < 4; mt++) {
                uint32_t base = ab + (uint32_t)((wm * 64 + mt * 16) * 80 + ks * 32) + loA;
                ldsm4(fah[mt], base + G_AH);
                ldsm4(fal[mt], base + G_AL);
            }
            #pragma unroll
            for (int np = 0; np < 2; np++) {
                uint32_t base = ab + (uint32_t)((wn * 32 + np * 16) * 80 + ks * 32) + loB;
                ldsm4(fbh[np], base + G_BH);
                ldsm4(fbl[np], base + G_BL);
            }
            #pragma unroll
            for (int mt = 0; mt < 4; mt++)
                #pragma unroll
                for (int nt = 0; nt < 4; nt++) {
                    const uint32_t* bh = &fbh[nt >> 1][(nt & 1) * 2];
                    const uint32_t* bl = &fbl[nt >> 1][(nt & 1) * 2];
                    mma_bf16(acc[mt][nt], fah[mt], bh);
                    mma_bf16(acc[mt][nt], fah[mt], bl);
                    mma_bf16(acc[mt][nt], fal[mt], bh);
                }
        }
    }

    #pragma unroll
    for (int mt = 0; mt < 4; mt++) {
        int r = row0 + wm * 64 + mt * 16 + g;
        if (mode == 0) {
            #pragma unroll
            for (int nt = 0; nt < 4; nt++) {
                int c = col0 + wn * 32 + nt * 8 + 2 * t;
                float2 bv = *(const float2*)&bias[c];
                float2 v0, v1;
                v0.x = acc[mt][nt][0] + bv.x; v0.y = acc[mt][nt][1] + bv.y;
                v1.x = acc[mt][nt][2] + bv.x; v1.y = acc[mt][nt][3] + bv.y;
                *(float2*)&C[(size_t)r * Nc + c]       = v0;
                *(float2*)&C[(size_t)(r + 8) * Nc + c] = v1;
            }
        } else {
            const int bb = r >> 11, nn = r & 2047;
            #pragma unroll
            for (int nt = 0; nt < 4; nt++) {
                int c = col0 + wn * 32 + nt * 8 + 2 * t;
                int h = c / 192, e = c % 192;
                float2 bv = *(const float2*)&bias[c];
                float x0 = acc[mt][nt][0] + bv.x, x1 = acc[mt][nt][1] + bv.y;
                float x2 = acc[mt][nt][2] + bv.x, x3 = acc[mt][nt][3] + bv.y;
                size_t bh = (size_t)bb * HH + h;
                if (e < 64) {
                    const float sc = 0.125f * LOG2E;
                    uint2 w0, w1;
                    w0.x = f2tf32(x0 * sc); w0.y = f2tf32(x1 * sc);
                    w1.x = f2tf32(x2 * sc); w1.y = f2tf32(x3 * sc);
                    *(uint2*)&g_q[(bh * NN + nn) * HDIM + e]       = w0;
                    *(uint2*)&g_q[(bh * NN + nn + 8) * HDIM + e]   = w1;
                } else if (e < 128) {
                    int d = e - 64;
                    uint2 w0, w1;
                    w0.x = f2tf32(x0); w0.y = f2tf32(x1);
                    w1.x = f2tf32(x2); w1.y = f2tf32(x3);
                    *(uint2*)&g_k[(bh * NN + nn) * HDIM + d]       = w0;
                    *(uint2*)&g_k[(bh * NN + nn + 8) * HDIM + d]   = w1;
                } else {
                    int d = e - 128;
                    size_t vb = (bh * HDIM + d) * NN;
                    g_vT[vb + nn]           = f2tf32(x0);
                    g_vT[vb + NN + nn]      = f2tf32(x1);
                    g_vT[vb + nn + 8]       = f2tf32(x2);
                    g_vT[vb + NN + nn + 8]  = f2tf32(x3);
                }
            }
        }
    }
}

// ============================================================================
// Flash attention v4: warp = 32 q-rows x 32 kv-cols (4 wq x 2 wk). B-frag
// reuse across 2 m-tiles; kv-split combined once at end (softmax is a pure
// sum — linear). 3-stage cp.async ring; 1 barrier + 1 syncwarp per tile.
// ============================================================================
#define AQ 0                              // Q then P: 128 x 272B = 34816
#define ABUF(i) (34816 + (i) * 34816)     // 3 stages: K(64x272) + V(64x272)
#define AK(i) ABUF(i)
#define AV(i) (ABUF(i) + 17408)
#define OEX ABUF(0)                       // post-loop: O-partial exchange
#define LEX ABUF(2)                       // post-loop: l exchange (128 floats)
#define AT_SMEM (34816 * 4)               // 139264

#define NT (NN / 64)                      // 32 kv tiles

__global__ __launch_bounds__(256) void attn_tc()
{
    extern __shared__ char sm[];
    uint32_t sb = smem_u32(sm);
    const int tid = threadIdx.x, wid = tid >> 5, lane = tid & 31;
    const int g = lane >> 2, t = lane & 3;
    const int wq = wid >> 1, wk = wid & 1;
    const int b = blockIdx.z, h = blockIdx.y, q0 = blockIdx.x * 128;
    const size_t bh = (size_t)b * HH + h;

    const uint32_t* gq = g_q  + bh * NN * HDIM;
    const uint32_t* gk = g_k  + bh * NN * HDIM;
    const uint32_t* gv = g_vT + bh * HDIM * NN;

    const int qr = tid >> 1, qc = tid & 1;
    const int kr = tid >> 2, kc = tid & 3;

    // group 0: Q + K0 + V0 ; group 1: K1 + V1
    {
        const uint32_t* qs = gq + (size_t)(q0 + qr) * HDIM + qc * 32;
        #pragma unroll
        for (int it = 0; it < 8; it++)
            cp16(sb + AQ + qr * 272 + qc * 128 + it * 16, qs + it * 4);
        const uint32_t* ks = gk + (size_t)kr * HDIM + kc * 16;
        const uint32_t* vs = gv + (size_t)kr * NN + kc * 16;
        #pragma unroll
        for (int it = 0; it < 4; it++) {
            cp16(sb + AK(0) + kr * 272 + kc * 64 + it * 16, ks + it * 4);
            cp16(sb + AV(0) + kr * 272 + kc * 64 + it * 16, vs + it * 4);
        }
        CP_COMMIT();
        ks = gk + (size_t)(64 + kr) * HDIM + kc * 16;
        vs = gv + (size_t)kr * NN + 64 + kc * 16;
        #pragma unroll
        for (int it = 0; it < 4; it++) {
            cp16(sb + AK(1) + kr * 272 + kc * 64 + it * 16, ks + it * 4);
            cp16(sb + AV(1) + kr * 272 + kc * 64 + it * 16, vs + it * 4);
        }
        CP_COMMIT();
    }

    const uint32_t loA = (uint32_t)(((lane & 7) + ((lane >> 3) & 1) * 8) * 272 + (lane >> 4) * 16);
    const uint32_t loB = (uint32_t)(((lane & 7) + (lane >> 4) * 8) * 272 + ((lane >> 3) & 1) * 16);

    uint32_t q[2][8][4];
    float o[2][8][4];
    #pragma unroll
    for (int mt = 0; mt < 2; mt++)
        #pragma unroll
        for (int nt = 0; nt < 8; nt++)
            #pragma unroll
            for (int j = 0; j < 4; j++) o[mt][nt][j] = 0.f;
    float lsum[2][2] = {{0.f, 0.f}, {0.f, 0.f}};

    for (int kt = 0; kt < NT; kt++) {
        if (kt < NT - 1) { CP_WAIT1(); } else { CP_WAIT0(); }
        __syncthreads();
        if (kt == 0) {
            #pragma unroll
            for (int mt = 0; mt < 2; mt++)
                #pragma unroll
                for (int kk = 0; kk < 8; kk++)
                    ldsm4(q[mt][kk],
                          sb + AQ + (uint32_t)((wq * 32 + mt * 16) * 272 + kk * 32) + loA);
        }
        if (kt + 2 < NT) {
            const int bu = (kt + 2) % 3;
            const uint32_t* ks = gk + (size_t)((kt + 2) * 64 + kr) * HDIM + kc * 16;
            const uint32_t* vs = gv + (size_t)kr * NN + (kt + 2) * 64 + kc * 16;
            #pragma unroll
            for (int it = 0; it < 4; it++) {
                cp16(sb + AK(bu) + kr * 272 + kc * 64 + it * 16, ks + it * 4);
                cp16(sb + AV(bu) + kr * 272 + kc * 64 + it * 16, vs + it * 4);
            }
            CP_COMMIT();
        }
        const uint32_t kbuf = sb + AK(kt % 3), vbuf = sb + AV(kt % 3);

        // ---- S = Q @ K^T over this warp's 32 kv cols; softmax fused per np ----
        #pragma unroll
        for (int np = 0; np < 2; np++) {
            float s00[4] = {0,0,0,0}, s01[4] = {0,0,0,0};
            float s10[4] = {0,0,0,0}, s11[4] = {0,0,0,0};
            #pragma unroll
            for (int kk = 0; kk < 8; kk++) {
                uint32_t kb[4];
                ldsm4(kb, kbuf + (uint32_t)((wk * 32 + np * 16) * 272 + kk * 32) + loB);
                mma_tf32(s00, q[0][kk], kb[0], kb[1]);
                mma_tf32(s01, q[0][kk], kb[2], kb[3]);
                mma_tf32(s10, q[1][kk], kb[0], kb[1]);
                mma_tf32(s11, q[1][kk], kb[2], kb[3]);
            }
            #define DO_BLOCK(sarr, mt, colbase) do {                                     \
                float a0 = ex2(sarr[0]), a1 = ex2(sarr[1]);                              \
                float a2 = ex2(sarr[2]), a3 = ex2(sarr[3]);                              \
                lsum[mt][0] += a0 + a1; lsum[mt][1] += a2 + a3;                          \
                uint2 w;                                                                 \
                uint32_t off = (uint32_t)((wq * 32 + (mt) * 16 + g) * 272 + wk * 128 +   \
                                          ((colbase) + 2 * t) * 4);                      \
                w.x = f2tf32(a0); w.y = f2tf32(a1);                                      \
                *(uint2*)(sm + AQ + off) = w;                                            \
                w.x = f2tf32(a2); w.y = f2tf32(a3);                                      \
                *(uint2*)(sm + AQ + off + 8 * 272) = w;                                  \
            } while (0)
            DO_BLOCK(s00, 0, np * 16);
            DO_BLOCK(s01, 0, np * 16 + 8);
            DO_BLOCK(s10, 1, np * 16);
            DO_BLOCK(s11, 1, np * 16 + 8);
        }
        __syncwarp();

        // ---- O += P @ V (warp's 32 kv rows of V, all 64 d cols) ----
        #pragma unroll
        for (int kk = 0; kk < 4; kk++) {
            uint32_t pa0[4], pa1[4];
            ldsm4(pa0, sb + AQ + (uint32_t)((wq * 32)      * 272 + wk * 128 + kk * 32) + loA);
            ldsm4(pa1, sb + AQ + (uint32_t)((wq * 32 + 16) * 272 + wk * 128 + kk * 32) + loA);
            #pragma unroll
            for (int np = 0; np < 4; np++) {
                uint32_t vb[4];
                ldsm4(vb, vbuf + (uint32_t)(np * 16 * 272 + wk * 128 + kk * 32) + loB);
                mma_tf32(o[0][2 * np],     pa0, vb[0], vb[1]);
                mma_tf32(o[0][2 * np + 1], pa0, vb[2], vb[3]);
                mma_tf32(o[1][2 * np],     pa1, vb[0], vb[1]);
                mma_tf32(o[1][2 * np + 1], pa1, vb[2], vb[3]);
            }
        }
    }

    // ---- quad-reduce l across t lanes ----
    #pragma unroll
    for (int mt = 0; mt < 2; mt++)
        #pragma unroll
        for (int hf = 0; hf < 2; hf++) {
            lsum[mt][hf] += __shfl_xor_sync(0xffffffffu, lsum[mt][hf], 1);
            lsum[mt][hf] += __shfl_xor_sync(0xffffffffu, lsum[mt][hf], 2);
        }

    // ---- combine kv halves: wk=1 exports, wk=0 merges + writes ----
    if (wk == 1) {
        #pragma unroll
        for (int mt = 0; mt < 2; mt++) {
            #pragma unroll
            for (int nt = 0; nt < 8; nt++) {
                uint32_t off = (uint32_t)((wq * 32 + mt * 16 + g) * 272 + (nt * 8 + 2 * t) * 4);
                float2 e0, e1;
                e0.x = o[mt][nt][0]; e0.y = o[mt][nt][1];
                e1.x = o[mt][nt][2]; e1.y = o[mt][nt][3];
                *(float2*)(sm + OEX + off)           = e0;
                *(float2*)(sm + OEX + off + 8 * 272) = e1;
            }
            if (t == 0) {
                *(float*)(sm + LEX + (wq * 32 + mt * 16 + g) * 4)     = lsum[mt][0];
                *(float*)(sm + LEX + (wq * 32 + mt * 16 + g + 8) * 4) = lsum[mt][1];
            }
        }
    }
    __syncthreads();
    if (wk == 0) {
        #pragma unroll
        for (int mt = 0; mt < 2; mt++) {
            float la = lsum[mt][0] + *(float*)(sm + LEX + (wq * 32 + mt * 16 + g) * 4);
            float lb = lsum[mt][1] + *(float*)(sm + LEX + (wq * 32 + mt * 16 + g + 8) * 4);
            const float inv0 = 1.0f / la, inv1 = 1.0f / lb;
            const int r0 = q0 + wq * 32 + mt * 16 + g;
            const size_t base0 = ((size_t)b * NN + r0) * DD + h * HDIM;
            const size_t base1 = base0 + (size_t)8 * DD;
            #pragma unroll
            for (int nt = 0; nt < 8; nt++) {
                uint32_t off = (uint32_t)((wq * 32 + mt * 16 + g) * 272 + (nt * 8 + 2 * t) * 4);
                float2 e0 = *(float2*)(sm + OEX + off);
                float2 e1 = *(float2*)(sm + OEX + off + 8 * 272);
                int c = nt * 8 + 2 * t;
                float x0 = (o[mt][nt][0] + e0.x) * inv0;
                float x1 = (o[mt][nt][1] + e0.y) * inv0;
                float x2 = (o[mt][nt][2] + e1.x) * inv1;
                float x3 = (o[mt][nt][3] + e1.y) * inv1;
                __nv_bfloat162 h0 = __floats2bfloat162_rn(x0, x1);
                __nv_bfloat162 l0b = __floats2bfloat162_rn(x0 - __bfloat162float(h0.x),
                                                           x1 - __bfloat162float(h0.y));
                __nv_bfloat162 h1 = __floats2bfloat162_rn(x2, x3);
                __nv_bfloat162 l1b = __floats2bfloat162_rn(x2 - __bfloat162float(h1.x),
                                                           x3 - __bfloat162float(h1.y));
                *(uint32_t*)&g_ah[base0 + c] = *(uint32_t*)&h0;
                *(uint32_t*)&g_al[base0 + c] = *(uint32_t*)&l0b;
                *(uint32_t*)&g_ah[base1 + c] = *(uint32_t*)&h1;
                *(uint32_t*)&g_al[base1 + c] = *(uint32_t*)&l1b;
            }
        }
    }
}

// ---------------------------------------------------------------------------
extern "C" void kernel_launch(void* const* d_in, const int* in_sizes, int n_in,
                              void* d_out, int out_size)
{
    const float* z    = (const float*)d_in[0];
    const float* Wqkv = (const float*)d_in[1];
    const float* bqkv = (const float*)d_in[2];
    const float* Wmsa = (const float*)d_in[3];
    const float* bmsa = (const float*)d_in[4];
    float* out = (float*)d_out;

    __nv_bfloat16 *zh, *zl, *ah, *al, *wqh, *wql, *wmh, *wml;
    cudaGetSymbolAddress((void**)&zh,  g_zh);  cudaGetSymbolAddress((void**)&zl,  g_zl);
    cudaGetSymbolAddress((void**)&ah,  g_ah);  cudaGetSymbolAddress((void**)&al,  g_al);
    cudaGetSymbolAddress((void**)&wqh, g_wqh); cudaGetSymbolAddress((void**)&wql, g_wql);
    cudaGetSymbolAddress((void**)&wmh, g_wmh); cudaGetSymbolAddress((void**)&wml, g_wml);

    cudaFuncSetAttribute(gemm_tc, cudaFuncAttributeMaxDynamicSharedMemorySize, G_SMEM);
    cudaFuncSetAttribute(attn_tc, cudaFuncAttributeMaxDynamicSharedMemorySize, AT_SMEM);

    const int total4 = N4_Z + N4_WQ + N4_WM;
    split_all<<<(total4 + 255) / 256, 256>>>(z, Wqkv, Wmsa);

    gemm_tc<<<dim3(RS / 128, MM / 128), 256, G_SMEM>>>(zh, zl, wqh, wql, bqkv,
                                                       out, RS, 1);
    attn_tc<<<dim3(NN / 128, HH, BB), 256, AT_SMEM>>>();
    gemm_tc<<<dim3(DD / 128, MM / 128), 256, G_SMEM>>>(ah, al, wmh, wml, bmsa,
                                                       out, DD, 0);
}

// round 8
// speedup vs baseline: 1.0456x; 1.0456x over previous
#include <cuda_runtime.h>
#include <cuda_bf16.h>
#include <math.h>
#include <stdint.h>

// ---------------- problem constants ----------------
#define BB   4
#define NN   2048
#define DD   768
#define HH   12
#define HDIM 64
#define RS   2304
#define MM   8192
#define KK   768
#define LOG2E 1.4426950408889634f

// ---------------- scratch ----------------
__device__ uint32_t g_q [(size_t)BB * HH * NN * HDIM];   // tf32, scaled
__device__ uint32_t g_k [(size_t)BB * HH * NN * HDIM];   // tf32
__device__ uint32_t g_vT[(size_t)BB * HH * HDIM * NN];   // tf32, transposed
__device__ __nv_bfloat16 g_zh[(size_t)MM * DD],  g_zl[(size_t)MM * DD];
__device__ __nv_bfloat16 g_ah[(size_t)MM * DD],  g_al[(size_t)MM * DD];
__device__ __nv_bfloat16 g_wqh[(size_t)RS * DD], g_wql[(size_t)RS * DD];
__device__ __nv_bfloat16 g_wmh[(size_t)DD * DD], g_wml[(size_t)DD * DD];

// ---------------- helpers ----------------
__device__ __forceinline__ uint32_t smem_u32(const void* p) {
    uint32_t a;
    asm("{ .reg .u64 t; cvta.to.shared.u64 t, %1; cvt.u32.u64 %0, t; }"
        : "=r"(a) : "l"(p));
    return a;
}
__device__ __forceinline__ void mma_bf16(float* c, const uint32_t* a, const uint32_t* b) {
    asm volatile("mma.sync.aligned.m16n8k16.row.col.f32.bf16.bf16.f32 "
        "{%0,%1,%2,%3}, {%4,%5,%6,%7}, {%8,%9}, {%0,%1,%2,%3};"
        : "+f"(c[0]), "+f"(c[1]), "+f"(c[2]), "+f"(c[3])
        : "r"(a[0]), "r"(a[1]), "r"(a[2]), "r"(a[3]), "r"(b[0]), "r"(b[1]));
}
__device__ __forceinline__ void mma_tf32(float* c, const uint32_t* a, uint32_t b0, uint32_t b1) {
    asm volatile("mma.sync.aligned.m16n8k8.row.col.f32.tf32.tf32.f32 "
        "{%0,%1,%2,%3}, {%4,%5,%6,%7}, {%8,%9}, {%0,%1,%2,%3};"
        : "+f"(c[0]), "+f"(c[1]), "+f"(c[2]), "+f"(c[3])
        : "r"(a[0]), "r"(a[1]), "r"(a[2]), "r"(a[3]), "r"(b0), "r"(b1));
}
__device__ __forceinline__ void ldsm4(uint32_t* r, uint32_t a) {
    asm volatile("ldmatrix.sync.aligned.m8n8.x4.shared.b16 {%0,%1,%2,%3}, [%4];"
        : "=r"(r[0]), "=r"(r[1]), "=r"(r[2]), "=r"(r[3]) : "r"(a));
}
__device__ __forceinline__ void cp16(uint32_t d, const void* s) {
    asm volatile("cp.async.cg.shared.global [%0], [%1], 16;" :: "r"(d), "l"(s));
}
#define CP_COMMIT() asm volatile("cp.async.commit_group;" ::: "memory")
#define CP_WAIT0()  asm volatile("cp.async.wait_group 0;" ::: "memory")

__device__ __forceinline__ uint32_t f2tf32(float x) {
    uint32_t r;
    asm("cvt.rna.tf32.f32 %0, %1;" : "=r"(r) : "f"(x));
    return r;
}
__device__ __forceinline__ float ex2(float x) {
    float y;
    asm("ex2.approx.f32 %0, %1;" : "=f"(y) : "f"(x));
    return y;
}

// ============================================================================
// Split pass (all three tensors in one launch): fp32 -> (hi, lo) bf16
// ============================================================================
#define N4_Z  (MM * DD / 4)
#define N4_WQ (RS * DD / 4)
#define N4_WM (DD * DD / 4)

__global__ __launch_bounds__(256) void split_all(
    const float* __restrict__ z, const float* __restrict__ wq,
    const float* __restrict__ wm)
{
    int i = blockIdx.x * blockDim.x + threadIdx.x;
    const float* src;
    __nv_bfloat16 *hi, *lo;
    if (i < N4_Z)                { src = z;  hi = g_zh;  lo = g_zl; }
    else if (i < N4_Z + N4_WQ)   { src = wq; hi = g_wqh; lo = g_wql; i -= N4_Z; }
    else if (i < N4_Z + N4_WQ + N4_WM) { src = wm; hi = g_wmh; lo = g_wml; i -= N4_Z + N4_WQ; }
    else return;
    float4 v = ((const float4*)src)[i];
    __nv_bfloat162 h0 = __floats2bfloat162_rn(v.x, v.y);
    __nv_bfloat162 h1 = __floats2bfloat162_rn(v.z, v.w);
    __nv_bfloat162 l0 = __floats2bfloat162_rn(v.x - __bfloat162float(h0.x),
                                              v.y - __bfloat162float(h0.y));
    __nv_bfloat162 l1 = __floats2bfloat162_rn(v.z - __bfloat162float(h1.x),
                                              v.w - __bfloat162float(h1.y));
    uint2 hp, lp;
    hp.x = *(uint32_t*)&h0; hp.y = *(uint32_t*)&h1;
    lp.x = *(uint32_t*)&l0; lp.y = *(uint32_t*)&l1;
    ((uint2*)hi)[i] = hp;
    ((uint2*)lo)[i] = lp;
}

// ============================================================================
// GEMM (pre-split bf16): 128x128 tile, BK=32, cp.async 2-buf, ldmatrix.
// Split terms emitted OUTERMOST: same-accumulator mma spacing = 16.
// ============================================================================
#define G_AH 0
#define G_AL 10240
#define G_BH 20480
#define G_BL 30720
#define G_BUF 40960
#define G_SMEM 81920

__global__ __launch_bounds__(256, 2) void gemm_tc(
    const __nv_bfloat16* __restrict__ Ah, const __nv_bfloat16* __restrict__ Al,
    const __nv_bfloat16* __restrict__ Bh, const __nv_bfloat16* __restrict__ Bl,
    const float* __restrict__ bias, float* __restrict__ C, int Nc, int mode)
{
    extern __shared__ char sm[];
    uint32_t sb = smem_u32(sm);
    const int tid = threadIdx.x, wid = tid >> 5, lane = tid & 31;
    const int g = lane >> 2, t = lane & 3;
    const int wm = wid >> 2, wn = wid & 3;
    const int row0 = blockIdx.y * 128, col0 = blockIdx.x * 128;

    const int sr = tid >> 2, sg = tid & 3;
    const size_t gaoff1 = (size_t)(row0 + sr) * KK + sg * 8;
    const size_t gaoff2 = (size_t)(row0 + sr + 64) * KK + sg * 8;
    const size_t gboff1 = (size_t)(col0 + sr) * KK + sg * 8;
    const size_t gboff2 = (size_t)(col0 + sr + 64) * KK + sg * 8;
    const uint32_t so1 = sr * 80 + sg * 16, so2 = (sr + 64) * 80 + sg * 16;

    const uint32_t loA = (uint32_t)(((lane & 7) + ((lane >> 3) & 1) * 8) * 80 + (lane >> 4) * 16);
    const uint32_t loB = (uint32_t)(((lane & 7) + (lane >> 4) * 8) * 80 + ((lane >> 3) & 1) * 16);

    float acc[4][4][4];
    #pragma unroll
    for (int mt = 0; mt < 4; mt++)
        #pragma unroll
        for (int nt = 0; nt < 4; nt++)
            #pragma unroll
            for (int j = 0; j < 4; j++) acc[mt][nt][j] = 0.f;

    {
        uint32_t d = sb;
        cp16(d + G_AH + so1, Ah + gaoff1); cp16(d + G_AH + so2, Ah + gaoff2);
        cp16(d + G_AL + so1, Al + gaoff1); cp16(d + G_AL + so2, Al + gaoff2);
        cp16(d + G_BH + so1, Bh + gboff1); cp16(d + G_BH + so2, Bh + gboff2);
        cp16(d + G_BL + so1, Bl + gboff1); cp16(d + G_BL + so2, Bl + gboff2);
        CP_COMMIT();
    }

    for (int i = 0; i < KK / 32; i++) {
        CP_WAIT0();
        __syncthreads();
        if (i + 1 < KK / 32) {
            const int ke = (i + 1) * 32;
            uint32_t d = sb + ((i + 1) & 1) * G_BUF;
            cp16(d + G_AH + so1, Ah + gaoff1 + ke); cp16(d + G_AH + so2, Ah + gaoff2 + ke);
            cp16(d + G_AL + so1, Al + gaoff1 + ke); cp16(d + G_AL + so2, Al + gaoff2 + ke);
            cp16(d + G_BH + so1, Bh + gboff1 + ke); cp16(d + G_BH + so2, Bh + gboff2 + ke);
            cp16(d + G_BL + so1, Bl + gboff1 + ke); cp16(d + G_BL + so2, Bl + gboff2 + ke);
            CP_COMMIT();
        }
        const uint32_t ab = sb + (i & 1) * G_BUF;
        #pragma unroll
        for (int ks = 0; ks < 2; ks++) {
            uint32_t fah[4][4], fal[4][4], fbh[2][4], fbl[2][4];
            #pragma unroll
            for (int mt = 0; mt < 4; mt++) {
                uint32_t base = ab + (uint32_t)((wm * 64 + mt * 16) * 80 + ks * 32) + loA;
                ldsm4(fah[mt], base + G_AH);
                ldsm4(fal[mt], base + G_AL);
            }
            #pragma unroll
            for (int np = 0; np < 2; np++) {
                uint32_t base = ab + (uint32_t)((wn * 32 + np * 16) * 80 + ks * 32) + loB;
                ldsm4(fbh[np], base + G_BH);
                ldsm4(fbl[np], base + G_BL);
            }
            // term 1: ah x bh (16 mmas, distinct accumulators)
            #pragma unroll
            for (int mt = 0; mt < 4; mt++)
                #pragma unroll
                for (int nt = 0; nt < 4; nt++)
                    mma_bf16(acc[mt][nt], fah[mt], &fbh[nt >> 1][(nt & 1) * 2]);
            // term 2: ah x bl
            #pragma unroll
            for (int mt = 0; mt < 4; mt++)
                #pragma unroll
                for (int nt = 0; nt < 4; nt++)
                    mma_bf16(acc[mt][nt], fah[mt], &fbl[nt >> 1][(nt & 1) * 2]);
            // term 3: al x bh
            #pragma unroll
            for (int mt = 0; mt < 4; mt++)
                #pragma unroll
                for (int nt = 0; nt < 4; nt++)
                    mma_bf16(acc[mt][nt], fal[mt], &fbh[nt >> 1][(nt & 1) * 2]);
        }
    }

    #pragma unroll
    for (int mt = 0; mt < 4; mt++) {
        int r = row0 + wm * 64 + mt * 16 + g;
        if (mode == 0) {
            #pragma unroll
            for (int nt = 0; nt < 4; nt++) {
                int c = col0 + wn * 32 + nt * 8 + 2 * t;
                float2 bv = *(const float2*)&bias[c];
                float2 v0, v1;
                v0.x = acc[mt][nt][0] + bv.x; v0.y = acc[mt][nt][1] + bv.y;
                v1.x = acc[mt][nt][2] + bv.x; v1.y = acc[mt][nt][3] + bv.y;
                *(float2*)&C[(size_t)r * Nc + c]       = v0;
                *(float2*)&C[(size_t)(r + 8) * Nc + c] = v1;
            }
        } else {
            const int bb = r >> 11, nn = r & 2047;
            #pragma unroll
            for (int nt = 0; nt < 4; nt++) {
                int c = col0 + wn * 32 + nt * 8 + 2 * t;
                int h = c / 192, e = c % 192;
                float2 bv = *(const float2*)&bias[c];
                float x0 = acc[mt][nt][0] + bv.x, x1 = acc[mt][nt][1] + bv.y;
                float x2 = acc[mt][nt][2] + bv.x, x3 = acc[mt][nt][3] + bv.y;
                size_t bh = (size_t)bb * HH + h;
                if (e < 64) {
                    const float sc = 0.125f * LOG2E;
                    uint2 w0, w1;
                    w0.x = f2tf32(x0 * sc); w0.y = f2tf32(x1 * sc);
                    w1.x = f2tf32(x2 * sc); w1.y = f2tf32(x3 * sc);
                    *(uint2*)&g_q[(bh * NN + nn) * HDIM + e]       = w0;
                    *(uint2*)&g_q[(bh * NN + nn + 8) * HDIM + e]   = w1;
                } else if (e < 128) {
                    int d = e - 64;
                    uint2 w0, w1;
                    w0.x = f2tf32(x0); w0.y = f2tf32(x1);
                    w1.x = f2tf32(x2); w1.y = f2tf32(x3);
                    *(uint2*)&g_k[(bh * NN + nn) * HDIM + d]       = w0;
                    *(uint2*)&g_k[(bh * NN + nn + 8) * HDIM + d]   = w1;
                } else {
                    int d = e - 128;
                    size_t vb = (bh * HDIM + d) * NN;
                    g_vT[vb + nn]           = f2tf32(x0);
                    g_vT[vb + NN + nn]      = f2tf32(x1);
                    g_vT[vb + nn + 8]       = f2tf32(x2);
                    g_vT[vb + NN + nn + 8]  = f2tf32(x3);
                }
            }
        }
    }
}

// ============================================================================
// Flash attention (R6 base): np-PAIRED S phase — 4 interleaved accumulators
// (same-acc spacing 4 mmas), ex2.approx softmax, cp.async 2-buf K/V^T.
// ============================================================================
#define AQ 0                            // Q then P: 128 x 272B
#define AK(b) (34816 + (b) * 17408)     // K: 64 x 272B, 2 bufs
#define AV(b) (69632 + (b) * 17408)     // V^T: 64 x 272B, 2 bufs
#define AT_SMEM 104448

__global__ __launch_bounds__(256, 2) void attn_tc()
{
    extern __shared__ char sm[];
    uint32_t sb = smem_u32(sm);
    const int tid = threadIdx.x, wid = tid >> 5, lane = tid & 31;
    const int g = lane >> 2, t = lane & 3;
    const int b = blockIdx.z, h = blockIdx.y, q0 = blockIdx.x * 128;
    const size_t bh = (size_t)b * HH + h;

    const uint32_t* gq = g_q  + bh * NN * HDIM;
    const uint32_t* gk = g_k  + bh * NN * HDIM;
    const uint32_t* gv = g_vT + bh * HDIM * NN;

    const int qr = tid >> 1, qc = tid & 1;
    const int kr = tid >> 2, kc = tid & 3;

    {
        const uint32_t* qs = gq + (size_t)(q0 + qr) * HDIM + qc * 32;
        #pragma unroll
        for (int it = 0; it < 8; it++)
            cp16(sb + AQ + qr * 272 + qc * 128 + it * 16, qs + it * 4);
        const uint32_t* ks = gk + (size_t)kr * HDIM + kc * 16;
        const uint32_t* vs = gv + (size_t)kr * NN + kc * 16;
        #pragma unroll
        for (int it = 0; it < 4; it++) {
            cp16(sb + AK(0) + kr * 272 + kc * 64 + it * 16, ks + it * 4);
            cp16(sb + AV(0) + kr * 272 + kc * 64 + it * 16, vs + it * 4);
        }
        CP_COMMIT();
    }

    const uint32_t loA = (uint32_t)(((lane & 7) + ((lane >> 3) & 1) * 8) * 272 + (lane >> 4) * 16);
    const uint32_t loB = (uint32_t)(((lane & 7) + (lane >> 4) * 8) * 272 + ((lane >> 3) & 1) * 16);
    const uint32_t qbase = sb + AQ + (uint32_t)(wid * 16 * 272) + loA;

    uint32_t q[8][4];
    float o[8][4];
    #pragma unroll
    for (int nt = 0; nt < 8; nt++)
        #pragma unroll
        for (int j = 0; j < 4; j++) o[nt][j] = 0.f;
    float l0 = 0.f, l1 = 0.f;

    for (int kt = 0; kt < NN / 64; kt++) {
        CP_WAIT0();
        __syncthreads();
        if (kt == 0) {
            #pragma unroll
            for (int kk = 0; kk < 8; kk++) ldsm4(q[kk], qbase + kk * 32);
        }
        if (kt + 1 < NN / 64) {
            const int buf = (kt + 1) & 1;
            const uint32_t* ks = gk + (size_t)((kt + 1) * 64 + kr) * HDIM + kc * 16;
            const uint32_t* vs = gv + (size_t)kr * NN + (kt + 1) * 64 + kc * 16;
            #pragma unroll
            for (int it = 0; it < 4; it++) {
                cp16(sb + AK(buf) + kr * 272 + kc * 64 + it * 16, ks + it * 4);
                cp16(sb + AV(buf) + kr * 272 + kc * 64 + it * 16, vs + it * 4);
            }
            CP_COMMIT();
        }
        const uint32_t kbuf = sb + AK(kt & 1), vbuf = sb + AV(kt & 1);

        // ---- S over np pairs: 4 accumulators interleaved ----
        float rs0 = 0.f, rs1 = 0.f;
        #pragma unroll
        for (int np2 = 0; np2 < 2; np2++) {
            float sA[4] = {0,0,0,0}, sB[4] = {0,0,0,0};
            float sC[4] = {0,0,0,0}, sD[4] = {0,0,0,0};
            #pragma unroll
            for (int kk = 0; kk < 8; kk++) {
                uint32_t kbx[4], kby[4];
                ldsm4(kbx, kbuf + (uint32_t)(((np2 * 2)     * 16) * 272 + kk * 32) + loB);
                ldsm4(kby, kbuf + (uint32_t)(((np2 * 2 + 1) * 16) * 272 + kk * 32) + loB);
                mma_tf32(sA, q[kk], kbx[0], kbx[1]);
                mma_tf32(sC, q[kk], kby[0], kby[1]);
                mma_tf32(sB, q[kk], kbx[2], kbx[3]);
                mma_tf32(sD, q[kk], kby[2], kby[3]);
            }
            #define SOFT_BLK(sarr, colbase) do {                                       \
                float a0 = ex2(sarr[0]), a1 = ex2(sarr[1]);                            \
                float a2 = ex2(sarr[2]), a3 = ex2(sarr[3]);                            \
                rs0 += a0 + a1; rs1 += a2 + a3;                                        \
                uint2 w;                                                               \
                uint32_t off = (uint32_t)((wid * 16 + g) * 272 + ((colbase) + 2 * t) * 4); \
                w.x = f2tf32(a0); w.y = f2tf32(a1);                                    \
                *(uint2*)(sm + AQ + off) = w;                                          \
                w.x = f2tf32(a2); w.y = f2tf32(a3);                                    \
                *(uint2*)(sm + AQ + off + 8 * 272) = w;                                \
            } while (0)
            SOFT_BLK(sA, np2 * 32);
            SOFT_BLK(sB, np2 * 32 + 8);
            SOFT_BLK(sC, np2 * 32 + 16);
            SOFT_BLK(sD, np2 * 32 + 24);
        }
        rs0 += __shfl_xor_sync(0xffffffffu, rs0, 1);
        rs0 += __shfl_xor_sync(0xffffffffu, rs0, 2);
        rs1 += __shfl_xor_sync(0xffffffffu, rs1, 1);
        rs1 += __shfl_xor_sync(0xffffffffu, rs1, 2);
        l0 += rs0; l1 += rs1;
        __syncwarp();

        // ---- O += P @ V (same-acc spacing 8) ----
        #pragma unroll
        for (int kk = 0; kk < 8; kk++) {
            uint32_t pa[4];
            ldsm4(pa, qbase + kk * 32);
            #pragma unroll
            for (int np = 0; np < 4; np++) {
                uint32_t vb[4];
                ldsm4(vb, vbuf + (uint32_t)(np * 16 * 272 + kk * 32) + loB);
                mma_tf32(o[2 * np],     pa, vb[0], vb[1]);
                mma_tf32(o[2 * np + 1], pa, vb[2], vb[3]);
            }
        }
    }

    // ---- normalize + write split bf16 ----
    const float inv0 = 1.0f / l0, inv1 = 1.0f / l1;
    const int r0 = q0 + wid * 16 + g;
    const size_t base0 = ((size_t)b * NN + r0) * DD + h * HDIM;
    const size_t base1 = base0 + (size_t)8 * DD;
    #pragma unroll
    for (int nt = 0; nt < 8; nt++) {
        int c = nt * 8 + 2 * t;
        float x0 = o[nt][0] * inv0, x1 = o[nt][1] * inv0;
        float x2 = o[nt][2] * inv1, x3 = o[nt][3] * inv1;
        __nv_bfloat162 h0 = __floats2bfloat162_rn(x0, x1);
        __nv_bfloat162 l0b = __floats2bfloat162_rn(x0 - __bfloat162float(h0.x),
                                                   x1 - __bfloat162float(h0.y));
        __nv_bfloat162 h1 = __floats2bfloat162_rn(x2, x3);
        __nv_bfloat162 l1b = __floats2bfloat162_rn(x2 - __bfloat162float(h1.x),
                                                   x3 - __bfloat162float(h1.y));
        *(uint32_t*)&g_ah[base0 + c] = *(uint32_t*)&h0;
        *(uint32_t*)&g_al[base0 + c] = *(uint32_t*)&l0b;
        *(uint32_t*)&g_ah[base1 + c] = *(uint32_t*)&h1;
        *(uint32_t*)&g_al[base1 + c] = *(uint32_t*)&l1b;
    }
}

// ---------------------------------------------------------------------------
extern "C" void kernel_launch(void* const* d_in, const int* in_sizes, int n_in,
                              void* d_out, int out_size)
{
    const float* z    = (const float*)d_in[0];
    const float* Wqkv = (const float*)d_in[1];
    const float* bqkv = (const float*)d_in[2];
    const float* Wmsa = (const float*)d_in[3];
    const float* bmsa = (const float*)d_in[4];
    float* out = (float*)d_out;

    __nv_bfloat16 *zh, *zl, *ah, *al, *wqh, *wql, *wmh, *wml;
    cudaGetSymbolAddress((void**)&zh,  g_zh);  cudaGetSymbolAddress((void**)&zl,  g_zl);
    cudaGetSymbolAddress((void**)&ah,  g_ah);  cudaGetSymbolAddress((void**)&al,  g_al);
    cudaGetSymbolAddress((void**)&wqh, g_wqh); cudaGetSymbolAddress((void**)&wql, g_wql);
    cudaGetSymbolAddress((void**)&wmh, g_wmh); cudaGetSymbolAddress((void**)&wml, g_wml);

    cudaFuncSetAttribute(gemm_tc, cudaFuncAttributeMaxDynamicSharedMemorySize, G_SMEM);
    cudaFuncSetAttribute(attn_tc, cudaFuncAttributeMaxDynamicSharedMemorySize, AT_SMEM);

    const int total4 = N4_Z + N4_WQ + N4_WM;
    split_all<<<(total4 + 255) / 256, 256>>>(z, Wqkv, Wmsa);

    gemm_tc<<<dim3(RS / 128, MM / 128), 256, G_SMEM>>>(zh, zl, wqh, wql, bqkv,
                                                       out, RS, 1);
    attn_tc<<<dim3(NN / 128, HH, BB), 256, AT_SMEM>>>();
    gemm_tc<<<dim3(DD / 128, MM / 128), 256, G_SMEM>>>(ah, al, wmh, wml, bmsa,
                                                       out, DD, 0);
}

// round 10
// speedup vs baseline: 1.4984x; 1.4330x over previous
#include <cuda_runtime.h>
#include <cuda_bf16.h>
#include <cuda_fp16.h>
#include <math.h>
#include <stdint.h>

// ---------------- problem constants ----------------
#define BB   4
#define NN   2048
#define DD   768
#define HH   12
#define HDIM 64
#define RS   2304
#define MM   8192
#define KK   768
#define LOG2E 1.4426950408889634f

// ---------------- scratch ----------------
__device__ __half g_q [(size_t)BB * HH * NN * HDIM];          // fp16, scaled
__device__ __half g_k [(size_t)BB * HH * NN * HDIM];          // fp16
__device__ __half g_vT[(size_t)BB * HH * HDIM * NN];          // fp16, transposed
__device__ __nv_bfloat16 g_zh[(size_t)MM * DD],  g_zl[(size_t)MM * DD];
__device__ __nv_bfloat16 g_ah[(size_t)MM * DD],  g_al[(size_t)MM * DD];
__device__ __nv_bfloat16 g_wqh[(size_t)RS * DD], g_wql[(size_t)RS * DD];
__device__ __nv_bfloat16 g_wmh[(size_t)DD * DD], g_wml[(size_t)DD * DD];

// ---------------- helpers ----------------
__device__ __forceinline__ uint32_t smem_u32(const void* p) {
    uint32_t a;
    asm("{ .reg .u64 t; cvta.to.shared.u64 t, %1; cvt.u32.u64 %0, t; }"
        : "=r"(a) : "l"(p));
    return a;
}
__device__ __forceinline__ void mma_bf16(float* c, const uint32_t* a, const uint32_t* b) {
    asm volatile("mma.sync.aligned.m16n8k16.row.col.f32.bf16.bf16.f32 "
        "{%0,%1,%2,%3}, {%4,%5,%6,%7}, {%8,%9}, {%0,%1,%2,%3};"
        : "+f"(c[0]), "+f"(c[1]), "+f"(c[2]), "+f"(c[3])
        : "r"(a[0]), "r"(a[1]), "r"(a[2]), "r"(a[3]), "r"(b[0]), "r"(b[1]));
}
__device__ __forceinline__ void mma_f16(float* c, const uint32_t* a, const uint32_t* b) {
    asm volatile("mma.sync.aligned.m16n8k16.row.col.f32.f16.f16.f32 "
        "{%0,%1,%2,%3}, {%4,%5,%6,%7}, {%8,%9}, {%0,%1,%2,%3};"
        : "+f"(c[0]), "+f"(c[1]), "+f"(c[2]), "+f"(c[3])
        : "r"(a[0]), "r"(a[1]), "r"(a[2]), "r"(a[3]), "r"(b[0]), "r"(b[1]));
}
__device__ __forceinline__ void ldsm4(uint32_t* r, uint32_t a) {
    asm volatile("ldmatrix.sync.aligned.m8n8.x4.shared.b16 {%0,%1,%2,%3}, [%4];"
        : "=r"(r[0]), "=r"(r[1]), "=r"(r[2]), "=r"(r[3]) : "r"(a));
}
__device__ __forceinline__ void cp16(uint32_t d, const void* s) {
    asm volatile("cp.async.cg.shared.global [%0], [%1], 16;" :: "r"(d), "l"(s));
}
#define CP_COMMIT() asm volatile("cp.async.commit_group;" ::: "memory")
#define CP_WAIT0()  asm volatile("cp.async.wait_group 0;" ::: "memory")

__device__ __forceinline__ float ex2(float x) {
    float y;
    asm("ex2.approx.f32 %0, %1;" : "=f"(y) : "f"(x));
    return y;
}

// ============================================================================
// Split pass (all three tensors in one launch): fp32 -> (hi, lo) bf16
// ============================================================================
#define N4_Z  (MM * DD / 4)
#define N4_WQ (RS * DD / 4)
#define N4_WM (DD * DD / 4)

__global__ __launch_bounds__(256) void split_all(
    const float* __restrict__ z, const float* __restrict__ wq,
    const float* __restrict__ wm)
{
    int i = blockIdx.x * blockDim.x + threadIdx.x;
    const float* src;
    __nv_bfloat16 *hi, *lo;
    if (i < N4_Z)                { src = z;  hi = g_zh;  lo = g_zl; }
    else if (i < N4_Z + N4_WQ)   { src = wq; hi = g_wqh; lo = g_wql; i -= N4_Z; }
    else if (i < N4_Z + N4_WQ + N4_WM) { src = wm; hi = g_wmh; lo = g_wml; i -= N4_Z + N4_WQ; }
    else return;
    float4 v = ((const float4*)src)[i];
    __nv_bfloat162 h0 = __floats2bfloat162_rn(v.x, v.y);
    __nv_bfloat162 h1 = __floats2bfloat162_rn(v.z, v.w);
    __nv_bfloat162 l0 = __floats2bfloat162_rn(v.x - __bfloat162float(h0.x),
                                              v.y - __bfloat162float(h0.y));
    __nv_bfloat162 l1 = __floats2bfloat162_rn(v.z - __bfloat162float(h1.x),
                                              v.w - __bfloat162float(h1.y));
    uint2 hp, lp;
    hp.x = *(uint32_t*)&h0; hp.y = *(uint32_t*)&h1;
    lp.x = *(uint32_t*)&l0; lp.y = *(uint32_t*)&l1;
    ((uint2*)hi)[i] = hp;
    ((uint2*)lo)[i] = lp;
}

// ============================================================================
// GEMM (pre-split bf16): 128x128 tile, BK=32, cp.async 2-buf, ldmatrix.
// mode 0: C = A@B^T + bias. mode 1: QKV epilogue (q/k/v^T fp16).
// ============================================================================
#define G_AH 0
#define G_AL 10240
#define G_BH 20480
#define G_BL 30720
#define G_BUF 40960
#define G_SMEM 81920

__global__ __launch_bounds__(256, 2) void gemm_tc(
    const __nv_bfloat16* __restrict__ Ah, const __nv_bfloat16* __restrict__ Al,
    const __nv_bfloat16* __restrict__ Bh, const __nv_bfloat16* __restrict__ Bl,
    const float* __restrict__ bias, float* __restrict__ C, int Nc, int mode)
{
    extern __shared__ char sm[];
    uint32_t sb = smem_u32(sm);
    const int tid = threadIdx.x, wid = tid >> 5, lane = tid & 31;
    const int g = lane >> 2, t = lane & 3;
    const int wm = wid >> 2, wn = wid & 3;
    const int row0 = blockIdx.y * 128, col0 = blockIdx.x * 128;

    const int sr = tid >> 2, sg = tid & 3;
    const size_t gaoff1 = (size_t)(row0 + sr) * KK + sg * 8;
    const size_t gaoff2 = (size_t)(row0 + sr + 64) * KK + sg * 8;
    const size_t gboff1 = (size_t)(col0 + sr) * KK + sg * 8;
    const size_t gboff2 = (size_t)(col0 + sr + 64) * KK + sg * 8;
    const uint32_t so1 = sr * 80 + sg * 16, so2 = (sr + 64) * 80 + sg * 16;

    const uint32_t loA = (uint32_t)(((lane & 7) + ((lane >> 3) & 1) * 8) * 80 + (lane >> 4) * 16);
    const uint32_t loB = (uint32_t)(((lane & 7) + (lane >> 4) * 8) * 80 + ((lane >> 3) & 1) * 16);

    float acc[4][4][4];
    #pragma unroll
    for (int mt = 0; mt < 4; mt++)
        #pragma unroll
        for (int nt = 0; nt < 4; nt++)
            #pragma unroll
            for (int j = 0; j < 4; j++) acc[mt][nt][j] = 0.f;

    {
        uint32_t d = sb;
        cp16(d + G_AH + so1, Ah + gaoff1); cp16(d + G_AH + so2, Ah + gaoff2);
        cp16(d + G_AL + so1, Al + gaoff1); cp16(d + G_AL + so2, Al + gaoff2);
        cp16(d + G_BH + so1, Bh + gboff1); cp16(d + G_BH + so2, Bh + gboff2);
        cp16(d + G_BL + so1, Bl + gboff1); cp16(d + G_BL + so2, Bl + gboff2);
        CP_COMMIT();
    }

    for (int i = 0; i < KK / 32; i++) {
        CP_WAIT0();
        __syncthreads();
        if (i + 1 < KK / 32) {
            const int ke = (i + 1) * 32;
            uint32_t d = sb + ((i + 1) & 1) * G_BUF;
            cp16(d + G_AH + so1, Ah + gaoff1 + ke); cp16(d + G_AH + so2, Ah + gaoff2 + ke);
            cp16(d + G_AL + so1, Al + gaoff1 + ke); cp16(d + G_AL + so2, Al + gaoff2 + ke);
            cp16(d + G_BH + so1, Bh + gboff1 + ke); cp16(d + G_BH + so2, Bh + gboff2 + ke);
            cp16(d + G_BL + so1, Bl + gboff1 + ke); cp16(d + G_BL + so2, Bl + gboff2 + ke);
            CP_COMMIT();
        }
        const uint32_t ab = sb + (i & 1) * G_BUF;
        #pragma unroll
        for (int ks = 0; ks < 2; ks++) {
            uint32_t fah[4][4], fal[4][4], fbh[2][4], fbl[2][4];
            #pragma unroll
            for (int mt = 0; mt < 4; mt++) {
                uint32_t base = ab + (uint32_t)((wm * 64 + mt * 16) * 80 + ks * 32) + loA;
                ldsm4(fah[mt], base + G_AH);
                ldsm4(fal[mt], base + G_AL);
            }
            #pragma unroll
            for (int np = 0; np < 2; np++) {
                uint32_t base = ab + (uint32_t)((wn * 32 + np * 16) * 80 + ks * 32) + loB;
                ldsm4(fbh[np], base + G_BH);
                ldsm4(fbl[np], base + G_BL);
            }
            #pragma unroll
            for (int mt = 0; mt < 4; mt++)
                #pragma unroll
                for (int nt = 0; nt < 4; nt++) {
                    const uint32_t* bh = &fbh[nt >> 1][(nt & 1) * 2];
                    const uint32_t* bl = &fbl[nt >> 1][(nt & 1) * 2];
                    mma_bf16(acc[mt][nt], fah[mt], bh);
                    mma_bf16(acc[mt][nt], fah[mt], bl);
                    mma_bf16(acc[mt][nt], fal[mt], bh);
                }
        }
    }

    #pragma unroll
    for (int mt = 0; mt < 4; mt++) {
        int r = row0 + wm * 64 + mt * 16 + g;
        if (mode == 0) {
            #pragma unroll
            for (int nt = 0; nt < 4; nt++) {
                int c = col0 + wn * 32 + nt * 8 + 2 * t;
                float2 bv = *(const float2*)&bias[c];
                float2 v0, v1;
                v0.x = acc[mt][nt][0] + bv.x; v0.y = acc[mt][nt][1] + bv.y;
                v1.x = acc[mt][nt][2] + bv.x; v1.y = acc[mt][nt][3] + bv.y;
                *(float2*)&C[(size_t)r * Nc + c]       = v0;
                *(float2*)&C[(size_t)(r + 8) * Nc + c] = v1;
            }
        } else {
            const int bb = r >> 11, nn = r & 2047;
            #pragma unroll
            for (int nt = 0; nt < 4; nt++) {
                int c = col0 + wn * 32 + nt * 8 + 2 * t;
                int h = c / 192, e = c % 192;
                float2 bv = *(const float2*)&bias[c];
                float x0 = acc[mt][nt][0] + bv.x, x1 = acc[mt][nt][1] + bv.y;
                float x2 = acc[mt][nt][2] + bv.x, x3 = acc[mt][nt][3] + bv.y;
                size_t bh = (size_t)bb * HH + h;
                if (e < 64) {
                    const float sc = 0.125f * LOG2E;
                    __half2 w0 = __floats2half2_rn(x0 * sc, x1 * sc);
                    __half2 w1 = __floats2half2_rn(x2 * sc, x3 * sc);
                    *(uint32_t*)&g_q[(bh * NN + nn) * HDIM + e]     = *(uint32_t*)&w0;
                    *(uint32_t*)&g_q[(bh * NN + nn + 8) * HDIM + e] = *(uint32_t*)&w1;
                } else if (e < 128) {
                    int d = e - 64;
                    __half2 w0 = __floats2half2_rn(x0, x1);
                    __half2 w1 = __floats2half2_rn(x2, x3);
                    *(uint32_t*)&g_k[(bh * NN + nn) * HDIM + d]     = *(uint32_t*)&w0;
                    *(uint32_t*)&g_k[(bh * NN + nn + 8) * HDIM + d] = *(uint32_t*)&w1;
                } else {
                    int d = e - 128;
                    size_t vb = (bh * HDIM + d) * NN;
                    g_vT[vb + nn]           = __float2half(x0);
                    g_vT[vb + NN + nn]      = __float2half(x1);
                    g_vT[vb + nn + 8]       = __float2half(x2);
                    g_vT[vb + NN + nn + 8]  = __float2half(x3);
                }
            }
        }
    }
}

// ============================================================================
// Flash attention v6: EVERYTHING fp16 (same mantissa as tf32, half the mmas).
// S and P·V both m16n8k16. cp.async 2-buf; 1 barrier + 1 syncwarp per tile.
// ============================================================================
#define AQ 0                              // Q fp16: 128 x 144B = 18432
#define AP 18432                          // P fp16: 128 x 144B = 18432
#define AK(b) (36864 + (b) * 9216)        // K fp16: 64 x 144B, 2 bufs
#define AV(b) (55296 + (b) * 9216)        // V^T fp16: 64 x 144B, 2 bufs
#define AT_SMEM 73728

__global__ __launch_bounds__(256, 2) void attn_tc()
{
    extern __shared__ char sm[];
    uint32_t sb = smem_u32(sm);
    const int tid = threadIdx.x, wid = tid >> 5, lane = tid & 31;
    const int g = lane >> 2, t = lane & 3;
    const int b = blockIdx.z, h = blockIdx.y, q0 = blockIdx.x * 128;
    const size_t bh = (size_t)b * HH + h;

    const __half* gq = g_q + bh * NN * HDIM;
    const __half* gk = g_k + bh * NN * HDIM;
    const __half* gv = g_vT + bh * HDIM * NN;

    const int qr = tid >> 1, qc = tid & 1;    // Q: 2 thr/row, 64B each
    const int kr = tid >> 2, kc = tid & 3;    // K/V: 4 thr/row, 32B each

    {
        const __half* qs = gq + (size_t)(q0 + qr) * HDIM + qc * 32;
        #pragma unroll
        for (int it = 0; it < 4; it++)
            cp16(sb + AQ + qr * 144 + qc * 64 + it * 16, qs + it * 8);
        const __half* ks = gk + (size_t)kr * HDIM + kc * 16;
        cp16(sb + AK(0) + kr * 144 + kc * 32,      ks);
        cp16(sb + AK(0) + kr * 144 + kc * 32 + 16, ks + 8);
        const __half* vs = gv + (size_t)kr * NN + kc * 16;
        cp16(sb + AV(0) + kr * 144 + kc * 32,      vs);
        cp16(sb + AV(0) + kr * 144 + kc * 32 + 16, vs + 8);
        CP_COMMIT();
    }

    const uint32_t loA = (uint32_t)(((lane & 7) + ((lane >> 3) & 1) * 8) * 144 + (lane >> 4) * 16);
    const uint32_t loB = (uint32_t)(((lane & 7) + (lane >> 4) * 8) * 144 + ((lane >> 3) & 1) * 16);
    const uint32_t qbase = sb + AQ + (uint32_t)(wid * 16 * 144) + loA;
    const uint32_t pbase = sb + AP + (uint32_t)(wid * 16 * 144) + loA;

    uint32_t q[4][4];
    float o[8][4];
    #pragma unroll
    for (int nt = 0; nt < 8; nt++)
        #pragma unroll
        for (int j = 0; j < 4; j++) o[nt][j] = 0.f;
    float l0 = 0.f, l1 = 0.f;

    for (int kt = 0; kt < NN / 64; kt++) {
        CP_WAIT0();
        __syncthreads();
        if (kt == 0) {
            #pragma unroll
            for (int kk = 0; kk < 4; kk++) ldsm4(q[kk], qbase + kk * 32);
        }
        if (kt + 1 < NN / 64) {
            const int buf = (kt + 1) & 1;
            const __half* ks = gk + (size_t)((kt + 1) * 64 + kr) * HDIM + kc * 16;
            cp16(sb + AK(buf) + kr * 144 + kc * 32,      ks);
            cp16(sb + AK(buf) + kr * 144 + kc * 32 + 16, ks + 8);
            const __half* vs = gv + (size_t)kr * NN + (kt + 1) * 64 + kc * 16;
            cp16(sb + AV(buf) + kr * 144 + kc * 32,      vs);
            cp16(sb + AV(buf) + kr * 144 + kc * 32 + 16, vs + 8);
            CP_COMMIT();
        }
        const uint32_t kbuf = sb + AK(kt & 1), vbuf = sb + AV(kt & 1);

        // ---- S = Q@K^T (fp16 m16n8k16), np-paired; softmax; P -> fp16 ----
        float rs0 = 0.f, rs1 = 0.f;
        #pragma unroll
        for (int np2 = 0; np2 < 2; np2++) {
            float sA[4] = {0,0,0,0}, sB[4] = {0,0,0,0};
            float sC[4] = {0,0,0,0}, sD[4] = {0,0,0,0};
            #pragma unroll
            for (int kk = 0; kk < 4; kk++) {
                uint32_t kbx[4], kby[4];
                ldsm4(kbx, kbuf + (uint32_t)((np2 * 32)      * 144 + kk * 32) + loB);
                ldsm4(kby, kbuf + (uint32_t)((np2 * 32 + 16) * 144 + kk * 32) + loB);
                mma_f16(sA, q[kk], &kbx[0]);
                mma_f16(sC, q[kk], &kby[0]);
                mma_f16(sB, q[kk], &kbx[2]);
                mma_f16(sD, q[kk], &kby[2]);
            }
            #define SOFT_BLK(sarr, colbase) do {                                       \
                float a0 = ex2(sarr[0]), a1 = ex2(sarr[1]);                            \
                float a2 = ex2(sarr[2]), a3 = ex2(sarr[3]);                            \
                rs0 += a0 + a1; rs1 += a2 + a3;                                        \
                __half2 pb0 = __floats2half2_rn(a0, a1);                               \
                __half2 pb1 = __floats2half2_rn(a2, a3);                               \
                uint32_t off = (uint32_t)((wid * 16 + g) * 144 + ((colbase) + 2 * t) * 2); \
                *(uint32_t*)(sm + AP + off)           = *(uint32_t*)&pb0;              \
                *(uint32_t*)(sm + AP + off + 8 * 144) = *(uint32_t*)&pb1;              \
            } while (0)
            SOFT_BLK(sA, np2 * 32);
            SOFT_BLK(sB, np2 * 32 + 8);
            SOFT_BLK(sC, np2 * 32 + 16);
            SOFT_BLK(sD, np2 * 32 + 24);
        }
        rs0 += __shfl_xor_sync(0xffffffffu, rs0, 1);
        rs0 += __shfl_xor_sync(0xffffffffu, rs0, 2);
        rs1 += __shfl_xor_sync(0xffffffffu, rs1, 1);
        rs1 += __shfl_xor_sync(0xffffffffu, rs1, 2);
        l0 += rs0; l1 += rs1;
        __syncwarp();

        // ---- O += P @ V (fp16 m16n8k16: 32 mmas) ----
        #pragma unroll
        for (int kk = 0; kk < 4; kk++) {
            uint32_t pa[4];
            ldsm4(pa, pbase + kk * 32);
            #pragma unroll
            for (int np = 0; np < 4; np++) {
                uint32_t vb[4];
                ldsm4(vb, vbuf + (uint32_t)(np * 16 * 144 + kk * 32) + loB);
                mma_f16(o[2 * np],     pa, &vb[0]);
                mma_f16(o[2 * np + 1], pa, &vb[2]);
            }
        }
    }

    // ---- normalize + write split bf16 ----
    const float inv0 = 1.0f / l0, inv1 = 1.0f / l1;
    const int r0 = q0 + wid * 16 + g;
    const size_t base0 = ((size_t)b * NN + r0) * DD + h * HDIM;
    const size_t base1 = base0 + (size_t)8 * DD;
    #pragma unroll
    for (int nt = 0; nt < 8; nt++) {
        int c = nt * 8 + 2 * t;
        float x0 = o[nt][0] * inv0, x1 = o[nt][1] * inv0;
        float x2 = o[nt][2] * inv1, x3 = o[nt][3] * inv1;
        __nv_bfloat162 h0 = __floats2bfloat162_rn(x0, x1);
        __nv_bfloat162 l0b = __floats2bfloat162_rn(x0 - __bfloat162float(h0.x),
                                                   x1 - __bfloat162float(h0.y));
        __nv_bfloat162 h1 = __floats2bfloat162_rn(x2, x3);
        __nv_bfloat162 l1b = __floats2bfloat162_rn(x2 - __bfloat162float(h1.x),
                                                   x3 - __bfloat162float(h1.y));
        *(uint32_t*)&g_ah[base0 + c] = *(uint32_t*)&h0;
        *(uint32_t*)&g_al[base0 + c] = *(uint32_t*)&l0b;
        *(uint32_t*)&g_ah[base1 + c] = *(uint32_t*)&h1;
        *(uint32_t*)&g_al[base1 + c] = *(uint32_t*)&l1b;
    }
}

// ---------------------------------------------------------------------------
extern "C" void kernel_launch(void* const* d_in, const int* in_sizes, int n_in,
                              void* d_out, int out_size)
{
    const float* z    = (const float*)d_in[0];
    const float* Wqkv = (const float*)d_in[1];
    const float* bqkv = (const float*)d_in[2];
    const float* Wmsa = (const float*)d_in[3];
    const float* bmsa = (const float*)d_in[4];
    float* out = (float*)d_out;

    __nv_bfloat16 *zh, *zl, *ah, *al, *wqh, *wql, *wmh, *wml;
    cudaGetSymbolAddress((void**)&zh,  g_zh);  cudaGetSymbolAddress((void**)&zl,  g_zl);
    cudaGetSymbolAddress((void**)&ah,  g_ah);  cudaGetSymbolAddress((void**)&al,  g_al);
    cudaGetSymbolAddress((void**)&wqh, g_wqh); cudaGetSymbolAddress((void**)&wql, g_wql);
    cudaGetSymbolAddress((void**)&wmh, g_wmh); cudaGetSymbolAddress((void**)&wml, g_wml);

    cudaFuncSetAttribute(gemm_tc, cudaFuncAttributeMaxDynamicSharedMemorySize, G_SMEM);
    cudaFuncSetAttribute(attn_tc, cudaFuncAttributeMaxDynamicSharedMemorySize, AT_SMEM);

    const int total4 = N4_Z + N4_WQ + N4_WM;
    split_all<<<(total4 + 255) / 256, 256>>>(z, Wqkv, Wmsa);

    gemm_tc<<<dim3(RS / 128, MM / 128), 256, G_SMEM>>>(zh, zl, wqh, wql, bqkv,
                                                       out, RS, 1);
    attn_tc<<<dim3(NN / 128, HH, BB), 256, AT_SMEM>>>();
    gemm_tc<<<dim3(DD / 128, MM / 128), 256, G_SMEM>>>(ah, al, wmh, wml, bmsa,
                                                       out, DD, 0);
}

// round 11
// speedup vs baseline: 1.8272x; 1.2195x over previous
#include <cuda_runtime.h>
#include <cuda_fp16.h>
#include <math.h>
#include <stdint.h>

// ---------------- problem constants ----------------
#define BB   4
#define NN   2048
#define DD   768
#define HH   12
#define HDIM 64
#define RS   2304
#define MM   8192
#define KK   768
#define LOG2E 1.4426950408889634f

// ---------------- scratch ----------------
__device__ __half g_q [(size_t)BB * HH * NN * HDIM];      // fp16, scaled
__device__ __half g_k [(size_t)BB * HH * NN * HDIM];      // fp16
__device__ __half g_vT[(size_t)BB * HH * HDIM * NN];      // fp16, transposed
__device__ __half g_z16 [(size_t)MM * DD];                // z, fp16
__device__ __half g_att16[(size_t)MM * DD];               // attention out, fp16
__device__ __half g_wqh[(size_t)RS * DD], g_wql[(size_t)RS * DD];
__device__ __half g_wmh[(size_t)DD * DD], g_wml[(size_t)DD * DD];

// ---------------- helpers ----------------
__device__ __forceinline__ uint32_t smem_u32(const void* p) {
    uint32_t a;
    asm("{ .reg .u64 t; cvta.to.shared.u64 t, %1; cvt.u32.u64 %0, t; }"
        : "=r"(a) : "l"(p));
    return a;
}
__device__ __forceinline__ void mma_f16(float* c, const uint32_t* a, const uint32_t* b) {
    asm volatile("mma.sync.aligned.m16n8k16.row.col.f32.f16.f16.f32 "
        "{%0,%1,%2,%3}, {%4,%5,%6,%7}, {%8,%9}, {%0,%1,%2,%3};"
        : "+f"(c[0]), "+f"(c[1]), "+f"(c[2]), "+f"(c[3])
        : "r"(a[0]), "r"(a[1]), "r"(a[2]), "r"(a[3]), "r"(b[0]), "r"(b[1]));
}
__device__ __forceinline__ void ldsm4(uint32_t* r, uint32_t a) {
    asm volatile("ldmatrix.sync.aligned.m8n8.x4.shared.b16 {%0,%1,%2,%3}, [%4];"
        : "=r"(r[0]), "=r"(r[1]), "=r"(r[2]), "=r"(r[3]) : "r"(a));
}
__device__ __forceinline__ void cp16(uint32_t d, const void* s) {
    asm volatile("cp.async.cg.shared.global [%0], [%1], 16;" :: "r"(d), "l"(s));
}
#define CP_COMMIT() asm volatile("cp.async.commit_group;" ::: "memory")
#define CP_WAIT0()  asm volatile("cp.async.wait_group 0;" ::: "memory")

__device__ __forceinline__ float ex2(float x) {
    float y;
    asm("ex2.approx.f32 %0, %1;" : "=f"(y) : "f"(x));
    return y;
}

// ============================================================================
// Split pass: z -> fp16; weights -> fp16 (hi, lo)
// ============================================================================
#define N4_Z  (MM * DD / 4)
#define N4_WQ (RS * DD / 4)
#define N4_WM (DD * DD / 4)

__global__ __launch_bounds__(256) void split_all(
    const float* __restrict__ z, const float* __restrict__ wq,
    const float* __restrict__ wm)
{
    int i = blockIdx.x * blockDim.x + threadIdx.x;
    if (i < N4_Z) {
        float4 v = ((const float4*)z)[i];
        __half2 a = __floats2half2_rn(v.x, v.y);
        __half2 b = __floats2half2_rn(v.z, v.w);
        uint2 p; p.x = *(uint32_t*)&a; p.y = *(uint32_t*)&b;
        ((uint2*)g_z16)[i] = p;
        return;
    }
    const float* src;
    __half *hi, *lo;
    if (i < N4_Z + N4_WQ) { src = wq; hi = g_wqh; lo = g_wql; i -= N4_Z; }
    else if (i < N4_Z + N4_WQ + N4_WM) { src = wm; hi = g_wmh; lo = g_wml; i -= N4_Z + N4_WQ; }
    else return;
    float4 v = ((const float4*)src)[i];
    __half2 h0 = __floats2half2_rn(v.x, v.y);
    __half2 h1 = __floats2half2_rn(v.z, v.w);
    __half2 l0 = __floats2half2_rn(v.x - __half2float(h0.x),
                                   v.y - __half2float(h0.y));
    __half2 l1 = __floats2half2_rn(v.z - __half2float(h1.x),
                                   v.w - __half2float(h1.y));
    uint2 hp, lp;
    hp.x = *(uint32_t*)&h0; hp.y = *(uint32_t*)&h1;
    lp.x = *(uint32_t*)&l0; lp.y = *(uint32_t*)&l1;
    ((uint2*)hi)[i] = hp;
    ((uint2*)lo)[i] = lp;
}

// ============================================================================
// GEMM: C = A @ (Bh+Bl)^T + bias. A single fp16, B split fp16.
// 128x128 tile, BK=32, cp.async 2-buf, ldmatrix. 32 mmas per ks (was 48).
// mode 0: fp32 C + bias. mode 1: QKV epilogue (q/k/v^T fp16).
// ============================================================================
#define G_A  0
#define G_BH 10240
#define G_BL 20480
#define G_BUF 30720
#define G_SMEM 61440

__global__ __launch_bounds__(256, 2) void gemm_tc(
    const __half* __restrict__ A,
    const __half* __restrict__ Bh, const __half* __restrict__ Bl,
    const float* __restrict__ bias, float* __restrict__ C, int Nc, int mode)
{
    extern __shared__ char sm[];
    uint32_t sb = smem_u32(sm);
    const int tid = threadIdx.x, wid = tid >> 5, lane = tid & 31;
    const int g = lane >> 2, t = lane & 3;
    const int wm = wid >> 2, wn = wid & 3;
    const int row0 = blockIdx.y * 128, col0 = blockIdx.x * 128;

    // staging: 1 row per thread (2 threads/row), 2 cp16 for A, 2 for Bh, 2 for Bl
    const int sr = tid >> 1, sseg = (tid & 1) * 2;     // 16B segs 0-1 or 2-3
    const size_t gaoff = (size_t)(row0 + sr) * KK + sseg * 8;
    const size_t gboff = (size_t)(col0 + sr) * KK + sseg * 8;
    const uint32_t soff = sr * 80 + sseg * 16;

    const uint32_t loA = (uint32_t)(((lane & 7) + ((lane >> 3) & 1) * 8) * 80 + (lane >> 4) * 16);
    const uint32_t loB = (uint32_t)(((lane & 7) + (lane >> 4) * 8) * 80 + ((lane >> 3) & 1) * 16);

    float acc[4][4][4];
    #pragma unroll
    for (int mt = 0; mt < 4; mt++)
        #pragma unroll
        for (int nt = 0; nt < 4; nt++)
            #pragma unroll
            for (int j = 0; j < 4; j++) acc[mt][nt][j] = 0.f;

    {
        uint32_t d = sb;
        cp16(d + G_A  + soff,      A  + gaoff);
        cp16(d + G_A  + soff + 16, A  + gaoff + 8);
        cp16(d + G_BH + soff,      Bh + gboff);
        cp16(d + G_BH + soff + 16, Bh + gboff + 8);
        cp16(d + G_BL + soff,      Bl + gboff);
        cp16(d + G_BL + soff + 16, Bl + gboff + 8);
        CP_COMMIT();
    }

    for (int i = 0; i < KK / 32; i++) {
        CP_WAIT0();
        __syncthreads();
        if (i + 1 < KK / 32) {
            const int ke = (i + 1) * 32;
            uint32_t d = sb + ((i + 1) & 1) * G_BUF;
            cp16(d + G_A  + soff,      A  + gaoff + ke);
            cp16(d + G_A  + soff + 16, A  + gaoff + ke + 8);
            cp16(d + G_BH + soff,      Bh + gboff + ke);
            cp16(d + G_BH + soff + 16, Bh + gboff + ke + 8);
            cp16(d + G_BL + soff,      Bl + gboff + ke);
            cp16(d + G_BL + soff + 16, Bl + gboff + ke + 8);
            CP_COMMIT();
        }
        const uint32_t ab = sb + (i & 1) * G_BUF;
        #pragma unroll
        for (int ks = 0; ks < 2; ks++) {
            uint32_t fa[4][4], fbh[2][4], fbl[2][4];
            #pragma unroll
            for (int mt = 0; mt < 4; mt++)
                ldsm4(fa[mt], ab + G_A + (uint32_t)((wm * 64 + mt * 16) * 80 + ks * 32) + loA);
            #pragma unroll
            for (int np = 0; np < 2; np++) {
                uint32_t base = ab + (uint32_t)((wn * 32 + np * 16) * 80 + ks * 32) + loB;
                ldsm4(fbh[np], base + G_BH);
                ldsm4(fbl[np], base + G_BL);
            }
            #pragma unroll
            for (int mt = 0; mt < 4; mt++)
                #pragma unroll
                for (int nt = 0; nt < 4; nt++) {
                    mma_f16(acc[mt][nt], fa[mt], &fbh[nt >> 1][(nt & 1) * 2]);
                    mma_f16(acc[mt][nt], fa[mt], &fbl[nt >> 1][(nt & 1) * 2]);
                }
        }
    }

    #pragma unroll
    for (int mt = 0; mt < 4; mt++) {
        int r = row0 + wm * 64 + mt * 16 + g;
        if (mode == 0) {
            #pragma unroll
            for (int nt = 0; nt < 4; nt++) {
                int c = col0 + wn * 32 + nt * 8 + 2 * t;
                float2 bv = *(const float2*)&bias[c];
                float2 v0, v1;
                v0.x = acc[mt][nt][0] + bv.x; v0.y = acc[mt][nt][1] + bv.y;
                v1.x = acc[mt][nt][2] + bv.x; v1.y = acc[mt][nt][3] + bv.y;
                *(float2*)&C[(size_t)r * Nc + c]       = v0;
                *(float2*)&C[(size_t)(r + 8) * Nc + c] = v1;
            }
        } else {
            const int bb = r >> 11, nn = r & 2047;
            #pragma unroll
            for (int nt = 0; nt < 4; nt++) {
                int c = col0 + wn * 32 + nt * 8 + 2 * t;
                int h = c / 192, e = c % 192;
                float2 bv = *(const float2*)&bias[c];
                float x0 = acc[mt][nt][0] + bv.x, x1 = acc[mt][nt][1] + bv.y;
                float x2 = acc[mt][nt][2] + bv.x, x3 = acc[mt][nt][3] + bv.y;
                size_t bh = (size_t)bb * HH + h;
                if (e < 64) {
                    const float sc = 0.125f * LOG2E;
                    __half2 w0 = __floats2half2_rn(x0 * sc, x1 * sc);
                    __half2 w1 = __floats2half2_rn(x2 * sc, x3 * sc);
                    *(uint32_t*)&g_q[(bh * NN + nn) * HDIM + e]     = *(uint32_t*)&w0;
                    *(uint32_t*)&g_q[(bh * NN + nn + 8) * HDIM + e] = *(uint32_t*)&w1;
                } else if (e < 128) {
                    int d = e - 64;
                    __half2 w0 = __floats2half2_rn(x0, x1);
                    __half2 w1 = __floats2half2_rn(x2, x3);
                    *(uint32_t*)&g_k[(bh * NN + nn) * HDIM + d]     = *(uint32_t*)&w0;
                    *(uint32_t*)&g_k[(bh * NN + nn + 8) * HDIM + d] = *(uint32_t*)&w1;
                } else {
                    int d = e - 128;
                    size_t vb = (bh * HDIM + d) * NN;
                    g_vT[vb + nn]           = __float2half(x0);
                    g_vT[vb + NN + nn]      = __float2half(x1);
                    g_vT[vb + nn + 8]       = __float2half(x2);
                    g_vT[vb + NN + nn + 8]  = __float2half(x3);
                }
            }
        }
    }
}

// ============================================================================
// Flash attention (all fp16 mma): unchanged from R10 except fp16 output.
// ============================================================================
#define AQ 0                              // Q fp16: 128 x 144B
#define AP 18432                          // P fp16: 128 x 144B
#define AK(b) (36864 + (b) * 9216)        // K fp16: 64 x 144B, 2 bufs
#define AV(b) (55296 + (b) * 9216)        // V^T fp16: 64 x 144B, 2 bufs
#define AT_SMEM 73728

__global__ __launch_bounds__(256, 2) void attn_tc()
{
    extern __shared__ char sm[];
    uint32_t sb = smem_u32(sm);
    const int tid = threadIdx.x, wid = tid >> 5, lane = tid & 31;
    const int g = lane >> 2, t = lane & 3;
    const int b = blockIdx.z, h = blockIdx.y, q0 = blockIdx.x * 128;
    const size_t bh = (size_t)b * HH + h;

    const __half* gq = g_q + bh * NN * HDIM;
    const __half* gk = g_k + bh * NN * HDIM;
    const __half* gv = g_vT + bh * HDIM * NN;

    const int qr = tid >> 1, qc = tid & 1;
    const int kr = tid >> 2, kc = tid & 3;

    {
        const __half* qs = gq + (size_t)(q0 + qr) * HDIM + qc * 32;
        #pragma unroll
        for (int it = 0; it < 4; it++)
            cp16(sb + AQ + qr * 144 + qc * 64 + it * 16, qs + it * 8);
        const __half* ks = gk + (size_t)kr * HDIM + kc * 16;
        cp16(sb + AK(0) + kr * 144 + kc * 32,      ks);
        cp16(sb + AK(0) + kr * 144 + kc * 32 + 16, ks + 8);
        const __half* vs = gv + (size_t)kr * NN + kc * 16;
        cp16(sb + AV(0) + kr * 144 + kc * 32,      vs);
        cp16(sb + AV(0) + kr * 144 + kc * 32 + 16, vs + 8);
        CP_COMMIT();
    }

    const uint32_t loA = (uint32_t)(((lane & 7) + ((lane >> 3) & 1) * 8) * 144 + (lane >> 4) * 16);
    const uint32_t loB = (uint32_t)(((lane & 7) + (lane >> 4) * 8) * 144 + ((lane >> 3) & 1) * 16);
    const uint32_t qbase = sb + AQ + (uint32_t)(wid * 16 * 144) + loA;
    const uint32_t pbase = sb + AP + (uint32_t)(wid * 16 * 144) + loA;

    uint32_t q[4][4];
    float o[8][4];
    #pragma unroll
    for (int nt = 0; nt < 8; nt++)
        #pragma unroll
        for (int j = 0; j < 4; j++) o[nt][j] = 0.f;
    float l0 = 0.f, l1 = 0.f;

    for (int kt = 0; kt < NN / 64; kt++) {
        CP_WAIT0();
        __syncthreads();
        if (kt == 0) {
            #pragma unroll
            for (int kk = 0; kk < 4; kk++) ldsm4(q[kk], qbase + kk * 32);
        }
        if (kt + 1 < NN / 64) {
            const int buf = (kt + 1) & 1;
            const __half* ks = gk + (size_t)((kt + 1) * 64 + kr) * HDIM + kc * 16;
            cp16(sb + AK(buf) + kr * 144 + kc * 32,      ks);
            cp16(sb + AK(buf) + kr * 144 + kc * 32 + 16, ks + 8);
            const __half* vs = gv + (size_t)kr * NN + (kt + 1) * 64 + kc * 16;
            cp16(sb + AV(buf) + kr * 144 + kc * 32,      vs);
            cp16(sb + AV(buf) + kr * 144 + kc * 32 + 16, vs + 8);
            CP_COMMIT();
        }
        const uint32_t kbuf = sb + AK(kt & 1), vbuf = sb + AV(kt & 1);

        float rs0 = 0.f, rs1 = 0.f;
        #pragma unroll
        for (int np2 = 0; np2 < 2; np2++) {
            float sA[4] = {0,0,0,0}, sB[4] = {0,0,0,0};
            float sC[4] = {0,0,0,0}, sD[4] = {0,0,0,0};
            #pragma unroll
            for (int kk = 0; kk < 4; kk++) {
                uint32_t kbx[4], kby[4];
                ldsm4(kbx, kbuf + (uint32_t)((np2 * 32)      * 144 + kk * 32) + loB);
                ldsm4(kby, kbuf + (uint32_t)((np2 * 32 + 16) * 144 + kk * 32) + loB);
                mma_f16(sA, q[kk], &kbx[0]);
                mma_f16(sC, q[kk], &kby[0]);
                mma_f16(sB, q[kk], &kbx[2]);
                mma_f16(sD, q[kk], &kby[2]);
            }
            #define SOFT_BLK(sarr, colbase) do {                                       \
                float a0 = ex2(sarr[0]), a1 = ex2(sarr[1]);                            \
                float a2 = ex2(sarr[2]), a3 = ex2(sarr[3]);                            \
                rs0 += a0 + a1; rs1 += a2 + a3;                                        \
                __half2 pb0 = __floats2half2_rn(a0, a1);                               \
                __half2 pb1 = __floats2half2_rn(a2, a3);                               \
                uint32_t off = (uint32_t)((wid * 16 + g) * 144 + ((colbase) + 2 * t) * 2); \
                *(uint32_t*)(sm + AP + off)           = *(uint32_t*)&pb0;              \
                *(uint32_t*)(sm + AP + off + 8 * 144) = *(uint32_t*)&pb1;              \
            } while (0)
            SOFT_BLK(sA, np2 * 32);
            SOFT_BLK(sB, np2 * 32 + 8);
            SOFT_BLK(sC, np2 * 32 + 16);
            SOFT_BLK(sD, np2 * 32 + 24);
        }
        rs0 += __shfl_xor_sync(0xffffffffu, rs0, 1);
        rs0 += __shfl_xor_sync(0xffffffffu, rs0, 2);
        rs1 += __shfl_xor_sync(0xffffffffu, rs1, 1);
        rs1 += __shfl_xor_sync(0xffffffffu, rs1, 2);
        l0 += rs0; l1 += rs1;
        __syncwarp();

        #pragma unroll
        for (int kk = 0; kk < 4; kk++) {
            uint32_t pa[4];
            ldsm4(pa, pbase + kk * 32);
            #pragma unroll
            for (int np = 0; np < 4; np++) {
                uint32_t vb[4];
                ldsm4(vb, vbuf + (uint32_t)(np * 16 * 144 + kk * 32) + loB);
                mma_f16(o[2 * np],     pa, &vb[0]);
                mma_f16(o[2 * np + 1], pa, &vb[2]);
            }
        }
    }

    // ---- normalize + write fp16 ----
    const float inv0 = 1.0f / l0, inv1 = 1.0f / l1;
    const int r0 = q0 + wid * 16 + g;
    const size_t base0 = ((size_t)b * NN + r0) * DD + h * HDIM;
    const size_t base1 = base0 + (size_t)8 * DD;
    #pragma unroll
    for (int nt = 0; nt < 8; nt++) {
        int c = nt * 8 + 2 * t;
        __half2 w0 = __floats2half2_rn(o[nt][0] * inv0, o[nt][1] * inv0);
        __half2 w1 = __floats2half2_rn(o[nt][2] * inv1, o[nt][3] * inv1);
        *(uint32_t*)&g_att16[base0 + c] = *(uint32_t*)&w0;
        *(uint32_t*)&g_att16[base1 + c] = *(uint32_t*)&w1;
    }
}

// ---------------------------------------------------------------------------
extern "C" void kernel_launch(void* const* d_in, const int* in_sizes, int n_in,
                              void* d_out, int out_size)
{
    const float* z    = (const float*)d_in[0];
    const float* Wqkv = (const float*)d_in[1];
    const float* bqkv = (const float*)d_in[2];
    const float* Wmsa = (const float*)d_in[3];
    const float* bmsa = (const float*)d_in[4];
    float* out = (float*)d_out;

    __half *z16, *att16, *wqh, *wql, *wmh, *wml;
    cudaGetSymbolAddress((void**)&z16,   g_z16);
    cudaGetSymbolAddress((void**)&att16, g_att16);
    cudaGetSymbolAddress((void**)&wqh, g_wqh); cudaGetSymbolAddress((void**)&wql, g_wql);
    cudaGetSymbolAddress((void**)&wmh, g_wmh); cudaGetSymbolAddress((void**)&wml, g_wml);

    cudaFuncSetAttribute(gemm_tc, cudaFuncAttributeMaxDynamicSharedMemorySize, G_SMEM);
    cudaFuncSetAttribute(attn_tc, cudaFuncAttributeMaxDynamicSharedMemorySize, AT_SMEM);

    const int total4 = N4_Z + N4_WQ + N4_WM;
    split_all<<<(total4 + 255) / 256, 256>>>(z, Wqkv, Wmsa);

    gemm_tc<<<dim3(RS / 128, MM / 128), 256, G_SMEM>>>(z16, wqh, wql, bqkv,
                                                       out, RS, 1);
    attn_tc<<<dim3(NN / 128, HH, BB), 256, AT_SMEM>>>();
    gemm_tc<<<dim3(DD / 128, MM / 128), 256, G_SMEM>>>(att16, wmh, wml, bmsa,
                                                       out, DD, 0);
}

// round 12
// speedup vs baseline: 2.2466x; 1.2295x over previous
#include <cuda_runtime.h>
#include <cuda_fp16.h>
#include <math.h>
#include <stdint.h>

// ---------------- problem constants ----------------
#define BB   4
#define NN   2048
#define DD   768
#define HH   12
#define HDIM 64
#define RS   2304
#define MM   8192
#define KK   768
#define LOG2E 1.4426950408889634f

// ---------------- scratch ----------------
__device__ __half g_q [(size_t)BB * HH * NN * HDIM];      // fp16, scaled
__device__ __half g_k [(size_t)BB * HH * NN * HDIM];      // fp16
__device__ __half g_vT[(size_t)BB * HH * HDIM * NN];      // fp16, transposed
__device__ __half g_z16 [(size_t)MM * DD];                // z, fp16
__device__ __half g_att16[(size_t)MM * DD];               // attention out, fp16
__device__ __half g_wq16[(size_t)RS * DD];                // Wqkv, fp16
__device__ __half g_wm16[(size_t)DD * DD];                // Wmsa, fp16

// ---------------- helpers ----------------
__device__ __forceinline__ uint32_t smem_u32(const void* p) {
    uint32_t a;
    asm("{ .reg .u64 t; cvta.to.shared.u64 t, %1; cvt.u32.u64 %0, t; }"
        : "=r"(a) : "l"(p));
    return a;
}
__device__ __forceinline__ void mma_f16(float* c, const uint32_t* a, const uint32_t* b) {
    asm volatile("mma.sync.aligned.m16n8k16.row.col.f32.f16.f16.f32 "
        "{%0,%1,%2,%3}, {%4,%5,%6,%7}, {%8,%9}, {%0,%1,%2,%3};"
        : "+f"(c[0]), "+f"(c[1]), "+f"(c[2]), "+f"(c[3])
        : "r"(a[0]), "r"(a[1]), "r"(a[2]), "r"(a[3]), "r"(b[0]), "r"(b[1]));
}
__device__ __forceinline__ void ldsm4(uint32_t* r, uint32_t a) {
    asm volatile("ldmatrix.sync.aligned.m8n8.x4.shared.b16 {%0,%1,%2,%3}, [%4];"
        : "=r"(r[0]), "=r"(r[1]), "=r"(r[2]), "=r"(r[3]) : "r"(a));
}
__device__ __forceinline__ void cp16(uint32_t d, const void* s) {
    asm volatile("cp.async.cg.shared.global [%0], [%1], 16;" :: "r"(d), "l"(s));
}
#define CP_COMMIT() asm volatile("cp.async.commit_group;" ::: "memory")
#define CP_WAIT0()  asm volatile("cp.async.wait_group 0;" ::: "memory")

__device__ __forceinline__ float ex2(float x) {
    float y;
    asm("ex2.approx.f32 %0, %1;" : "=f"(y) : "f"(x));
    return y;
}

// ============================================================================
// Convert pass: z, Wqkv, Wmsa -> fp16 (single)
// ============================================================================
#define N4_Z  (MM * DD / 4)
#define N4_WQ (RS * DD / 4)
#define N4_WM (DD * DD / 4)

__global__ __launch_bounds__(256) void cvt_all(
    const float* __restrict__ z, const float* __restrict__ wq,
    const float* __restrict__ wm)
{
    int i = blockIdx.x * blockDim.x + threadIdx.x;
    const float* src;
    __half* dst;
    if (i < N4_Z)                      { src = z;  dst = g_z16; }
    else if (i < N4_Z + N4_WQ)         { src = wq; dst = g_wq16; i -= N4_Z; }
    else if (i < N4_Z + N4_WQ + N4_WM) { src = wm; dst = g_wm16; i -= N4_Z + N4_WQ; }
    else return;
    float4 v = ((const float4*)src)[i];
    __half2 a = __floats2half2_rn(v.x, v.y);
    __half2 b = __floats2half2_rn(v.z, v.w);
    uint2 p; p.x = *(uint32_t*)&a; p.y = *(uint32_t*)&b;
    ((uint2*)dst)[i] = p;
}

// ============================================================================
// GEMM: C = A @ B^T + bias. Plain fp16, fp32 accumulate.
// 128x128 tile, BK=32, cp.async 2-buf, ldmatrix. 16 mmas per ks.
// mode 0: fp32 C + bias. mode 1: QKV epilogue (q/k/v^T fp16).
// ============================================================================
#define G_A  0
#define G_B  10240
#define G_BUF 20480
#define G_SMEM 40960

__global__ __launch_bounds__(256, 2) void gemm_tc(
    const __half* __restrict__ A, const __half* __restrict__ B,
    const float* __restrict__ bias, float* __restrict__ C, int Nc, int mode)
{
    extern __shared__ char sm[];
    uint32_t sb = smem_u32(sm);
    const int tid = threadIdx.x, wid = tid >> 5, lane = tid & 31;
    const int g = lane >> 2, t = lane & 3;
    const int wm = wid >> 2, wn = wid & 3;
    const int row0 = blockIdx.y * 128, col0 = blockIdx.x * 128;

    // staging: 2 threads/row, each 2x cp16 per stream
    const int sr = tid >> 1, sseg = (tid & 1) * 2;
    const size_t gaoff = (size_t)(row0 + sr) * KK + sseg * 8;
    const size_t gboff = (size_t)(col0 + sr) * KK + sseg * 8;
    const uint32_t soff = sr * 80 + sseg * 16;

    const uint32_t loA = (uint32_t)(((lane & 7) + ((lane >> 3) & 1) * 8) * 80 + (lane >> 4) * 16);
    const uint32_t loB = (uint32_t)(((lane & 7) + (lane >> 4) * 8) * 80 + ((lane >> 3) & 1) * 16);

    float acc[4][4][4];
    #pragma unroll
    for (int mt = 0; mt < 4; mt++)
        #pragma unroll
        for (int nt = 0; nt < 4; nt++)
            #pragma unroll
            for (int j = 0; j < 4; j++) acc[mt][nt][j] = 0.f;

    {
        uint32_t d = sb;
        cp16(d + G_A + soff,      A + gaoff);
        cp16(d + G_A + soff + 16, A + gaoff + 8);
        cp16(d + G_B + soff,      B + gboff);
        cp16(d + G_B + soff + 16, B + gboff + 8);
        CP_COMMIT();
    }

    for (int i = 0; i < KK / 32; i++) {
        CP_WAIT0();
        __syncthreads();
        if (i + 1 < KK / 32) {
            const int ke = (i + 1) * 32;
            uint32_t d = sb + ((i + 1) & 1) * G_BUF;
            cp16(d + G_A + soff,      A + gaoff + ke);
            cp16(d + G_A + soff + 16, A + gaoff + ke + 8);
            cp16(d + G_B + soff,      B + gboff + ke);
            cp16(d + G_B + soff + 16, B + gboff + ke + 8);
            CP_COMMIT();
        }
        const uint32_t ab = sb + (i & 1) * G_BUF;
        #pragma unroll
        for (int ks = 0; ks < 2; ks++) {
            uint32_t fa[4][4], fb[2][4];
            #pragma unroll
            for (int mt = 0; mt < 4; mt++)
                ldsm4(fa[mt], ab + G_A + (uint32_t)((wm * 64 + mt * 16) * 80 + ks * 32) + loA);
            #pragma unroll
            for (int np = 0; np < 2; np++)
                ldsm4(fb[np], ab + G_B + (uint32_t)((wn * 32 + np * 16) * 80 + ks * 32) + loB);
            #pragma unroll
            for (int mt = 0; mt < 4; mt++)
                #pragma unroll
                for (int nt = 0; nt < 4; nt++)
                    mma_f16(acc[mt][nt], fa[mt], &fb[nt >> 1][(nt & 1) * 2]);
        }
    }

    #pragma unroll
    for (int mt = 0; mt < 4; mt++) {
        int r = row0 + wm * 64 + mt * 16 + g;
        if (mode == 0) {
            #pragma unroll
            for (int nt = 0; nt < 4; nt++) {
                int c = col0 + wn * 32 + nt * 8 + 2 * t;
                float2 bv = *(const float2*)&bias[c];
                float2 v0, v1;
                v0.x = acc[mt][nt][0] + bv.x; v0.y = acc[mt][nt][1] + bv.y;
                v1.x = acc[mt][nt][2] + bv.x; v1.y = acc[mt][nt][3] + bv.y;
                *(float2*)&C[(size_t)r * Nc + c]       = v0;
                *(float2*)&C[(size_t)(r + 8) * Nc + c] = v1;
            }
        } else {
            const int bb = r >> 11, nn = r & 2047;
            #pragma unroll
            for (int nt = 0; nt < 4; nt++) {
                int c = col0 + wn * 32 + nt * 8 + 2 * t;
                int h = c / 192, e = c % 192;
                float2 bv = *(const float2*)&bias[c];
                float x0 = acc[mt][nt][0] + bv.x, x1 = acc[mt][nt][1] + bv.y;
                float x2 = acc[mt][nt][2] + bv.x, x3 = acc[mt][nt][3] + bv.y;
                size_t bh = (size_t)bb * HH + h;
                if (e < 64) {
                    const float sc = 0.125f * LOG2E;
                    __half2 w0 = __floats2half2_rn(x0 * sc, x1 * sc);
                    __half2 w1 = __floats2half2_rn(x2 * sc, x3 * sc);
                    *(uint32_t*)&g_q[(bh * NN + nn) * HDIM + e]     = *(uint32_t*)&w0;
                    *(uint32_t*)&g_q[(bh * NN + nn + 8) * HDIM + e] = *(uint32_t*)&w1;
                } else if (e < 128) {
                    int d = e - 64;
                    __half2 w0 = __floats2half2_rn(x0, x1);
                    __half2 w1 = __floats2half2_rn(x2, x3);
                    *(uint32_t*)&g_k[(bh * NN + nn) * HDIM + d]     = *(uint32_t*)&w0;
                    *(uint32_t*)&g_k[(bh * NN + nn + 8) * HDIM + d] = *(uint32_t*)&w1;
                } else {
                    int d = e - 128;
                    size_t vb = (bh * HDIM + d) * NN;
                    g_vT[vb + nn]           = __float2half(x0);
                    g_vT[vb + NN + nn]      = __float2half(x1);
                    g_vT[vb + nn + 8]       = __float2half(x2);
                    g_vT[vb + NN + nn + 8]  = __float2half(x3);
                }
            }
        }
    }
}

// ============================================================================
// Flash attention (all fp16 mma) — unchanged from R11.
// ============================================================================
#define AQ 0                              // Q fp16: 128 x 144B
#define AP 18432                          // P fp16: 128 x 144B
#define AK(b) (36864 + (b) * 9216)        // K fp16: 64 x 144B, 2 bufs
#define AV(b) (55296 + (b) * 9216)        // V^T fp16: 64 x 144B, 2 bufs
#define AT_SMEM 73728

__global__ __launch_bounds__(256, 2) void attn_tc()
{
    extern __shared__ char sm[];
    uint32_t sb = smem_u32(sm);
    const int tid = threadIdx.x, wid = tid >> 5, lane = tid & 31;
    const int g = lane >> 2, t = lane & 3;
    const int b = blockIdx.z, h = blockIdx.y, q0 = blockIdx.x * 128;
    const size_t bh = (size_t)b * HH + h;

    const __half* gq = g_q + bh * NN * HDIM;
    const __half* gk = g_k + bh * NN * HDIM;
    const __half* gv = g_vT + bh * HDIM * NN;

    const int qr = tid >> 1, qc = tid & 1;
    const int kr = tid >> 2, kc = tid & 3;

    {
        const __half* qs = gq + (size_t)(q0 + qr) * HDIM + qc * 32;
        #pragma unroll
        for (int it = 0; it < 4; it++)
            cp16(sb + AQ + qr * 144 + qc * 64 + it * 16, qs + it * 8);
        const __half* ks = gk + (size_t)kr * HDIM + kc * 16;
        cp16(sb + AK(0) + kr * 144 + kc * 32,      ks);
        cp16(sb + AK(0) + kr * 144 + kc * 32 + 16, ks + 8);
        const __half* vs = gv + (size_t)kr * NN + kc * 16;
        cp16(sb + AV(0) + kr * 144 + kc * 32,      vs);
        cp16(sb + AV(0) + kr * 144 + kc * 32 + 16, vs + 8);
        CP_COMMIT();
    }

    const uint32_t loA = (uint32_t)(((lane & 7) + ((lane >> 3) & 1) * 8) * 144 + (lane >> 4) * 16);
    const uint32_t loB = (uint32_t)(((lane & 7) + (lane >> 4) * 8) * 144 + ((lane >> 3) & 1) * 16);
    const uint32_t qbase = sb + AQ + (uint32_t)(wid * 16 * 144) + loA;
    const uint32_t pbase = sb + AP + (uint32_t)(wid * 16 * 144) + loA;

    uint32_t q[4][4];
    float o[8][4];
    #pragma unroll
    for (int nt = 0; nt < 8; nt++)
        #pragma unroll
        for (int j = 0; j < 4; j++) o[nt][j] = 0.f;
    float l0 = 0.f, l1 = 0.f;

    for (int kt = 0; kt < NN / 64; kt++) {
        CP_WAIT0();
        __syncthreads();
        if (kt == 0) {
            #pragma unroll
            for (int kk = 0; kk < 4; kk++) ldsm4(q[kk], qbase + kk * 32);
        }
        if (kt + 1 < NN / 64) {
            const int buf = (kt + 1) & 1;
            const __half* ks = gk + (size_t)((kt + 1) * 64 + kr) * HDIM + kc * 16;
            cp16(sb + AK(buf) + kr * 144 + kc * 32,      ks);
            cp16(sb + AK(buf) + kr * 144 + kc * 32 + 16, ks + 8);
            const __half* vs = gv + (size_t)kr * NN + (kt + 1) * 64 + kc * 16;
            cp16(sb + AV(buf) + kr * 144 + kc * 32,      vs);
            cp16(sb + AV(buf) + kr * 144 + kc * 32 + 16, vs + 8);
            CP_COMMIT();
        }
        const uint32_t kbuf = sb + AK(kt & 1), vbuf = sb + AV(kt & 1);

        float rs0 = 0.f, rs1 = 0.f;
        #pragma unroll
        for (int np2 = 0; np2 < 2; np2++) {
            float sA[4] = {0,0,0,0}, sB[4] = {0,0,0,0};
            float sC[4] = {0,0,0,0}, sD[4] = {0,0,0,0};
            #pragma unroll
            for (int kk = 0; kk < 4; kk++) {
                uint32_t kbx[4], kby[4];
                ldsm4(kbx, kbuf + (uint32_t)((np2 * 32)      * 144 + kk * 32) + loB);
                ldsm4(kby, kbuf + (uint32_t)((np2 * 32 + 16) * 144 + kk * 32) + loB);
                mma_f16(sA, q[kk], &kbx[0]);
                mma_f16(sC, q[kk], &kby[0]);
                mma_f16(sB, q[kk], &kbx[2]);
                mma_f16(sD, q[kk], &kby[2]);
            }
            #define SOFT_BLK(sarr, colbase) do {                                       \
                float a0 = ex2(sarr[0]), a1 = ex2(sarr[1]);                            \
                float a2 = ex2(sarr[2]), a3 = ex2(sarr[3]);                            \
                rs0 += a0 + a1; rs1 += a2 + a3;                                        \
                __half2 pb0 = __floats2half2_rn(a0, a1);                               \
                __half2 pb1 = __floats2half2_rn(a2, a3);                               \
                uint32_t off = (uint32_t)((wid * 16 + g) * 144 + ((colbase) + 2 * t) * 2); \
                *(uint32_t*)(sm + AP + off)           = *(uint32_t*)&pb0;              \
                *(uint32_t*)(sm + AP + off + 8 * 144) = *(uint32_t*)&pb1;              \
            } while (0)
            SOFT_BLK(sA, np2 * 32);
            SOFT_BLK(sB, np2 * 32 + 8);
            SOFT_BLK(sC, np2 * 32 + 16);
            SOFT_BLK(sD, np2 * 32 + 24);
        }
        rs0 += __shfl_xor_sync(0xffffffffu, rs0, 1);
        rs0 += __shfl_xor_sync(0xffffffffu, rs0, 2);
        rs1 += __shfl_xor_sync(0xffffffffu, rs1, 1);
        rs1 += __shfl_xor_sync(0xffffffffu, rs1, 2);
        l0 += rs0; l1 += rs1;
        __syncwarp();

        #pragma unroll
        for (int kk = 0; kk < 4; kk++) {
            uint32_t pa[4];
            ldsm4(pa, pbase + kk * 32);
            #pragma unroll
            for (int np = 0; np < 4; np++) {
                uint32_t vb[4];
                ldsm4(vb, vbuf + (uint32_t)(np * 16 * 144 + kk * 32) + loB);
                mma_f16(o[2 * np],     pa, &vb[0]);
                mma_f16(o[2 * np + 1], pa, &vb[2]);
            }
        }
    }

    const float inv0 = 1.0f / l0, inv1 = 1.0f / l1;
    const int r0 = q0 + wid * 16 + g;
    const size_t base0 = ((size_t)b * NN + r0) * DD + h * HDIM;
    const size_t base1 = base0 + (size_t)8 * DD;
    #pragma unroll
    for (int nt = 0; nt < 8; nt++) {
        int c = nt * 8 + 2 * t;
        __half2 w0 = __floats2half2_rn(o[nt][0] * inv0, o[nt][1] * inv0);
        __half2 w1 = __floats2half2_rn(o[nt][2] * inv1, o[nt][3] * inv1);
        *(uint32_t*)&g_att16[base0 + c] = *(uint32_t*)&w0;
        *(uint32_t*)&g_att16[base1 + c] = *(uint32_t*)&w1;
    }
}

// ---------------------------------------------------------------------------
extern "C" void kernel_launch(void* const* d_in, const int* in_sizes, int n_in,
                              void* d_out, int out_size)
{
    const float* z    = (const float*)d_in[0];
    const float* Wqkv = (const float*)d_in[1];
    const float* bqkv = (const float*)d_in[2];
    const float* Wmsa = (const float*)d_in[3];
    const float* bmsa = (const float*)d_in[4];
    float* out = (float*)d_out;

    __half *z16, *att16, *wq16, *wm16;
    cudaGetSymbolAddress((void**)&z16,   g_z16);
    cudaGetSymbolAddress((void**)&att16, g_att16);
    cudaGetSymbolAddress((void**)&wq16,  g_wq16);
    cudaGetSymbolAddress((void**)&wm16,  g_wm16);

    cudaFuncSetAttribute(gemm_tc, cudaFuncAttributeMaxDynamicSharedMemorySize, G_SMEM);
    cudaFuncSetAttribute(attn_tc, cudaFuncAttributeMaxDynamicSharedMemorySize, AT_SMEM);

    const int total4 = N4_Z + N4_WQ + N4_WM;
    cvt_all<<<(total4 + 255) / 256, 256>>>(z, Wqkv, Wmsa);

    gemm_tc<<<dim3(RS / 128, MM / 128), 256, G_SMEM>>>(z16, wq16, bqkv,
                                                       out, RS, 1);
    attn_tc<<<dim3(NN / 128, HH, BB), 256, AT_SMEM>>>();
    gemm_tc<<<dim3(DD / 128, MM / 128), 256, G_SMEM>>>(att16, wm16, bmsa,
                                                       out, DD, 0);
}

// round 13
// speedup vs baseline: 2.2895x; 1.0191x over previous
#include <cuda_runtime.h>
#include <cuda_fp16.h>
#include <math.h>
#include <stdint.h>

// ---------------- problem constants ----------------
#define BB   4
#define NN   2048
#define DD   768
#define HH   12
#define HDIM 64
#define RS   2304
#define MM   8192
#define KK   768
#define LOG2E 1.4426950408889634f

// ---------------- scratch ----------------
__device__ __half g_q [(size_t)BB * HH * NN * HDIM];      // fp16, scaled
__device__ __half g_k [(size_t)BB * HH * NN * HDIM];      // fp16
__device__ __half g_vT[(size_t)BB * HH * HDIM * NN];      // fp16, transposed
__device__ __half g_z16 [(size_t)MM * DD];                // z, fp16
__device__ __half g_att16[(size_t)MM * DD];               // attention out, fp16
__device__ __half g_wq16[(size_t)RS * DD];                // Wqkv, fp16
__device__ __half g_wm16[(size_t)DD * DD];                // Wmsa, fp16

// ---------------- helpers ----------------
__device__ __forceinline__ uint32_t smem_u32(const void* p) {
    uint32_t a;
    asm("{ .reg .u64 t; cvta.to.shared.u64 t, %1; cvt.u32.u64 %0, t; }"
        : "=r"(a) : "l"(p));
    return a;
}
__device__ __forceinline__ void mma_f16(float* c, const uint32_t* a, const uint32_t* b) {
    asm volatile("mma.sync.aligned.m16n8k16.row.col.f32.f16.f16.f32 "
        "{%0,%1,%2,%3}, {%4,%5,%6,%7}, {%8,%9}, {%0,%1,%2,%3};"
        : "+f"(c[0]), "+f"(c[1]), "+f"(c[2]), "+f"(c[3])
        : "r"(a[0]), "r"(a[1]), "r"(a[2]), "r"(a[3]), "r"(b[0]), "r"(b[1]));
}
// fp16 accumulator variant: d/c are 2x .f16x2 regs; runs at full HMMA rate.
__device__ __forceinline__ void mma_f16acc(uint32_t* c, const uint32_t* a, const uint32_t* b) {
    asm volatile("mma.sync.aligned.m16n8k16.row.col.f16.f16.f16.f16 "
        "{%0,%1}, {%2,%3,%4,%5}, {%6,%7}, {%0,%1};"
        : "+r"(c[0]), "+r"(c[1])
        : "r"(a[0]), "r"(a[1]), "r"(a[2]), "r"(a[3]), "r"(b[0]), "r"(b[1]));
}
__device__ __forceinline__ void ldsm4(uint32_t* r, uint32_t a) {
    asm volatile("ldmatrix.sync.aligned.m8n8.x4.shared.b16 {%0,%1,%2,%3}, [%4];"
        : "=r"(r[0]), "=r"(r[1]), "=r"(r[2]), "=r"(r[3]) : "r"(a));
}
__device__ __forceinline__ void cp16(uint32_t d, const void* s) {
    asm volatile("cp.async.cg.shared.global [%0], [%1], 16;" :: "r"(d), "l"(s));
}
#define CP_COMMIT() asm volatile("cp.async.commit_group;" ::: "memory")
#define CP_WAIT0()  asm volatile("cp.async.wait_group 0;" ::: "memory")

__device__ __forceinline__ uint32_t ex2_h2(uint32_t x) {
    uint32_t y;
    asm("ex2.approx.f16x2 %0, %1;" : "=r"(y) : "r"(x));
    return y;
}

// ============================================================================
// Convert pass: z, Wqkv, Wmsa -> fp16 (single)
// ============================================================================
#define N4_Z  (MM * DD / 4)
#define N4_WQ (RS * DD / 4)
#define N4_WM (DD * DD / 4)

__global__ __launch_bounds__(256) void cvt_all(
    const float* __restrict__ z, const float* __restrict__ wq,
    const float* __restrict__ wm)
{
    int i = blockIdx.x * blockDim.x + threadIdx.x;
    const float* src;
    __half* dst;
    if (i < N4_Z)                      { src = z;  dst = g_z16; }
    else if (i < N4_Z + N4_WQ)         { src = wq; dst = g_wq16; i -= N4_Z; }
    else if (i < N4_Z + N4_WQ + N4_WM) { src = wm; dst = g_wm16; i -= N4_Z + N4_WQ; }
    else return;
    float4 v = ((const float4*)src)[i];
    __half2 a = __floats2half2_rn(v.x, v.y);
    __half2 b = __floats2half2_rn(v.z, v.w);
    uint2 p; p.x = *(uint32_t*)&a; p.y = *(uint32_t*)&b;
    ((uint2*)dst)[i] = p;
}

// ============================================================================
// GEMM: C = A @ B^T + bias. Plain fp16, fp32 accumulate. (unchanged R12)
// ============================================================================
#define G_A  0
#define G_B  10240
#define G_BUF 20480
#define G_SMEM 40960

__global__ __launch_bounds__(256, 2) void gemm_tc(
    const __half* __restrict__ A, const __half* __restrict__ B,
    const float* __restrict__ bias, float* __restrict__ C, int Nc, int mode)
{
    extern __shared__ char sm[];
    uint32_t sb = smem_u32(sm);
    const int tid = threadIdx.x, wid = tid >> 5, lane = tid & 31;
    const int g = lane >> 2, t = lane & 3;
    const int wm = wid >> 2, wn = wid & 3;
    const int row0 = blockIdx.y * 128, col0 = blockIdx.x * 128;

    const int sr = tid >> 1, sseg = (tid & 1) * 2;
    const size_t gaoff = (size_t)(row0 + sr) * KK + sseg * 8;
    const size_t gboff = (size_t)(col0 + sr) * KK + sseg * 8;
    const uint32_t soff = sr * 80 + sseg * 16;

    const uint32_t loA = (uint32_t)(((lane & 7) + ((lane >> 3) & 1) * 8) * 80 + (lane >> 4) * 16);
    const uint32_t loB = (uint32_t)(((lane & 7) + (lane >> 4) * 8) * 80 + ((lane >> 3) & 1) * 16);

    float acc[4][4][4];
    #pragma unroll
    for (int mt = 0; mt < 4; mt++)
        #pragma unroll
        for (int nt = 0; nt < 4; nt++)
            #pragma unroll
            for (int j = 0; j < 4; j++) acc[mt][nt][j] = 0.f;

    {
        uint32_t d = sb;
        cp16(d + G_A + soff,      A + gaoff);
        cp16(d + G_A + soff + 16, A + gaoff + 8);
        cp16(d + G_B + soff,      B + gboff);
        cp16(d + G_B + soff + 16, B + gboff + 8);
        CP_COMMIT();
    }

    for (int i = 0; i < KK / 32; i++) {
        CP_WAIT0();
        __syncthreads();
        if (i + 1 < KK / 32) {
            const int ke = (i + 1) * 32;
            uint32_t d = sb + ((i + 1) & 1) * G_BUF;
            cp16(d + G_A + soff,      A + gaoff + ke);
            cp16(d + G_A + soff + 16, A + gaoff + ke + 8);
            cp16(d + G_B + soff,      B + gboff + ke);
            cp16(d + G_B + soff + 16, B + gboff + ke + 8);
            CP_COMMIT();
        }
        const uint32_t ab = sb + (i & 1) * G_BUF;
        #pragma unroll
        for (int ks = 0; ks < 2; ks++) {
            uint32_t fa[4][4], fb[2][4];
            #pragma unroll
            for (int mt = 0; mt < 4; mt++)
                ldsm4(fa[mt], ab + G_A + (uint32_t)((wm * 64 + mt * 16) * 80 + ks * 32) + loA);
            #pragma unroll
            for (int np = 0; np < 2; np++)
                ldsm4(fb[np], ab + G_B + (uint32_t)((wn * 32 + np * 16) * 80 + ks * 32) + loB);
            #pragma unroll
            for (int mt = 0; mt < 4; mt++)
                #pragma unroll
                for (int nt = 0; nt < 4; nt++)
                    mma_f16(acc[mt][nt], fa[mt], &fb[nt >> 1][(nt & 1) * 2]);
        }
    }

    #pragma unroll
    for (int mt = 0; mt < 4; mt++) {
        int r = row0 + wm * 64 + mt * 16 + g;
        if (mode == 0) {
            #pragma unroll
            for (int nt = 0; nt < 4; nt++) {
                int c = col0 + wn * 32 + nt * 8 + 2 * t;
                float2 bv = *(const float2*)&bias[c];
                float2 v0, v1;
                v0.x = acc[mt][nt][0] + bv.x; v0.y = acc[mt][nt][1] + bv.y;
                v1.x = acc[mt][nt][2] + bv.x; v1.y = acc[mt][nt][3] + bv.y;
                *(float2*)&C[(size_t)r * Nc + c]       = v0;
                *(float2*)&C[(size_t)(r + 8) * Nc + c] = v1;
            }
        } else {
            const int bb = r >> 11, nn = r & 2047;
            #pragma unroll
            for (int nt = 0; nt < 4; nt++) {
                int c = col0 + wn * 32 + nt * 8 + 2 * t;
                int h = c / 192, e = c % 192;
                float2 bv = *(const float2*)&bias[c];
                float x0 = acc[mt][nt][0] + bv.x, x1 = acc[mt][nt][1] + bv.y;
                float x2 = acc[mt][nt][2] + bv.x, x3 = acc[mt][nt][3] + bv.y;
                size_t bh = (size_t)bb * HH + h;
                if (e < 64) {
                    const float sc = 0.125f * LOG2E;
                    __half2 w0 = __floats2half2_rn(x0 * sc, x1 * sc);
                    __half2 w1 = __floats2half2_rn(x2 * sc, x3 * sc);
                    *(uint32_t*)&g_q[(bh * NN + nn) * HDIM + e]     = *(uint32_t*)&w0;
                    *(uint32_t*)&g_q[(bh * NN + nn + 8) * HDIM + e] = *(uint32_t*)&w1;
                } else if (e < 128) {
                    int d = e - 64;
                    __half2 w0 = __floats2half2_rn(x0, x1);
                    __half2 w1 = __floats2half2_rn(x2, x3);
                    *(uint32_t*)&g_k[(bh * NN + nn) * HDIM + d]     = *(uint32_t*)&w0;
                    *(uint32_t*)&g_k[(bh * NN + nn + 8) * HDIM + d] = *(uint32_t*)&w1;
                } else {
                    int d = e - 128;
                    size_t vb = (bh * HDIM + d) * NN;
                    g_vT[vb + nn]           = __float2half(x0);
                    g_vT[vb + NN + nn]      = __float2half(x1);
                    g_vT[vb + nn + 8]       = __float2half(x2);
                    g_vT[vb + NN + nn + 8]  = __float2half(x3);
                }
            }
        }
    }
}

// ============================================================================
// Flash attention v7: S with fp16 accumulator (full-rate HMMA) + f16x2 softmax.
// P·V keeps fp32 accumulator (spans 2048 keys). cp.async 2-buf K/V^T.
// ============================================================================
#define AQ 0                              // Q fp16: 128 x 144B
#define AP 18432                          // P fp16: 128 x 144B
#define AK(b) (36864 + (b) * 9216)        // K fp16: 64 x 144B, 2 bufs
#define AV(b) (55296 + (b) * 9216)        // V^T fp16: 64 x 144B, 2 bufs
#define AT_SMEM 73728

__global__ __launch_bounds__(256, 2) void attn_tc()
{
    extern __shared__ char sm[];
    uint32_t sb = smem_u32(sm);
    const int tid = threadIdx.x, wid = tid >> 5, lane = tid & 31;
    const int g = lane >> 2, t = lane & 3;
    const int b = blockIdx.z, h = blockIdx.y, q0 = blockIdx.x * 128;
    const size_t bh = (size_t)b * HH + h;

    const __half* gq = g_q + bh * NN * HDIM;
    const __half* gk = g_k + bh * NN * HDIM;
    const __half* gv = g_vT + bh * HDIM * NN;

    const int qr = tid >> 1, qc = tid & 1;
    const int kr = tid >> 2, kc = tid & 3;

    {
        const __half* qs = gq + (size_t)(q0 + qr) * HDIM + qc * 32;
        #pragma unroll
        for (int it = 0; it < 4; it++)
            cp16(sb + AQ + qr * 144 + qc * 64 + it * 16, qs + it * 8);
        const __half* ks = gk + (size_t)kr * HDIM + kc * 16;
        cp16(sb + AK(0) + kr * 144 + kc * 32,      ks);
        cp16(sb + AK(0) + kr * 144 + kc * 32 + 16, ks + 8);
        const __half* vs = gv + (size_t)kr * NN + kc * 16;
        cp16(sb + AV(0) + kr * 144 + kc * 32,      vs);
        cp16(sb + AV(0) + kr * 144 + kc * 32 + 16, vs + 8);
        CP_COMMIT();
    }

    const uint32_t loA = (uint32_t)(((lane & 7) + ((lane >> 3) & 1) * 8) * 144 + (lane >> 4) * 16);
    const uint32_t loB = (uint32_t)(((lane & 7) + (lane >> 4) * 8) * 144 + ((lane >> 3) & 1) * 16);
    const uint32_t qbase = sb + AQ + (uint32_t)(wid * 16 * 144) + loA;
    const uint32_t pbase = sb + AP + (uint32_t)(wid * 16 * 144) + loA;

    uint32_t q[4][4];
    float o[8][4];
    #pragma unroll
    for (int nt = 0; nt < 8; nt++)
        #pragma unroll
        for (int j = 0; j < 4; j++) o[nt][j] = 0.f;
    float l0 = 0.f, l1 = 0.f;

    for (int kt = 0; kt < NN / 64; kt++) {
        CP_WAIT0();
        __syncthreads();
        if (kt == 0) {
            #pragma unroll
            for (int kk = 0; kk < 4; kk++) ldsm4(q[kk], qbase + kk * 32);
        }
        if (kt + 1 < NN / 64) {
            const int buf = (kt + 1) & 1;
            const __half* ks = gk + (size_t)((kt + 1) * 64 + kr) * HDIM + kc * 16;
            cp16(sb + AK(buf) + kr * 144 + kc * 32,      ks);
            cp16(sb + AK(buf) + kr * 144 + kc * 32 + 16, ks + 8);
            const __half* vs = gv + (size_t)kr * NN + (kt + 1) * 64 + kc * 16;
            cp16(sb + AV(buf) + kr * 144 + kc * 32,      vs);
            cp16(sb + AV(buf) + kr * 144 + kc * 32 + 16, vs + 8);
            CP_COMMIT();
        }
        const uint32_t kbuf = sb + AK(kt & 1), vbuf = sb + AV(kt & 1);

        // ---- S = Q@K^T (fp16 acc, full-rate); f16x2 softmax; P -> smem ----
        float rs0 = 0.f, rs1 = 0.f;
        #pragma unroll
        for (int np2 = 0; np2 < 2; np2++) {
            uint32_t sA[2] = {0, 0}, sB[2] = {0, 0};
            uint32_t sC[2] = {0, 0}, sD[2] = {0, 0};
            #pragma unroll
            for (int kk = 0; kk < 4; kk++) {
                uint32_t kbx[4], kby[4];
                ldsm4(kbx, kbuf + (uint32_t)((np2 * 32)      * 144 + kk * 32) + loB);
                ldsm4(kby, kbuf + (uint32_t)((np2 * 32 + 16) * 144 + kk * 32) + loB);
                mma_f16acc(sA, q[kk], &kbx[0]);
                mma_f16acc(sC, q[kk], &kby[0]);
                mma_f16acc(sB, q[kk], &kbx[2]);
                mma_f16acc(sD, q[kk], &kby[2]);
            }
            #define SOFT_BLK(sacc, colbase) do {                                       \
                uint32_t p0 = ex2_h2(sacc[0]);                                         \
                uint32_t p1 = ex2_h2(sacc[1]);                                         \
                float2 f0 = __half22float2(*(__half2*)&p0);                            \
                float2 f1 = __half22float2(*(__half2*)&p1);                            \
                rs0 += f0.x + f0.y; rs1 += f1.x + f1.y;                                \
                uint32_t off = (uint32_t)((wid * 16 + g) * 144 + ((colbase) + 2 * t) * 2); \
                *(uint32_t*)(sm + AP + off)           = p0;                            \
                *(uint32_t*)(sm + AP + off + 8 * 144) = p1;                            \
            } while (0)
            SOFT_BLK(sA, np2 * 32);
            SOFT_BLK(sB, np2 * 32 + 8);
            SOFT_BLK(sC, np2 * 32 + 16);
            SOFT_BLK(sD, np2 * 32 + 24);
        }
        rs0 += __shfl_xor_sync(0xffffffffu, rs0, 1);
        rs0 += __shfl_xor_sync(0xffffffffu, rs0, 2);
        rs1 += __shfl_xor_sync(0xffffffffu, rs1, 1);
        rs1 += __shfl_xor_sync(0xffffffffu, rs1, 2);
        l0 += rs0; l1 += rs1;
        __syncwarp();

        // ---- O += P @ V (fp32 acc — spans all 2048 keys) ----
        #pragma unroll
        for (int kk = 0; kk < 4; kk++) {
            uint32_t pa[4];
            ldsm4(pa, pbase + kk * 32);
            #pragma unroll
            for (int np = 0; np < 4; np++) {
                uint32_t vb[4];
                ldsm4(vb, vbuf + (uint32_t)(np * 16 * 144 + kk * 32) + loB);
                mma_f16(o[2 * np],     pa, &vb[0]);
                mma_f16(o[2 * np + 1], pa, &vb[2]);
            }
        }
    }

    const float inv0 = 1.0f / l0, inv1 = 1.0f / l1;
    const int r0 = q0 + wid * 16 + g;
    const size_t base0 = ((size_t)b * NN + r0) * DD + h * HDIM;
    const size_t base1 = base0 + (size_t)8 * DD;
    #pragma unroll
    for (int nt = 0; nt < 8; nt++) {
        int c = nt * 8 + 2 * t;
        __half2 w0 = __floats2half2_rn(o[nt][0] * inv0, o[nt][1] * inv0);
        __half2 w1 = __floats2half2_rn(o[nt][2] * inv1, o[nt][3] * inv1);
        *(uint32_t*)&g_att16[base0 + c] = *(uint32_t*)&w0;
        *(uint32_t*)&g_att16[base1 + c] = *(uint32_t*)&w1;
    }
}

// ---------------------------------------------------------------------------
extern "C" void kernel_launch(void* const* d_in, const int* in_sizes, int n_in,
                              void* d_out, int out_size)
{
    const float* z    = (const float*)d_in[0];
    const float* Wqkv = (const float*)d_in[1];
    const float* bqkv = (const float*)d_in[2];
    const float* Wmsa = (const float*)d_in[3];
    const float* bmsa = (const float*)d_in[4];
    float* out = (float*)d_out;

    __half *z16, *att16, *wq16, *wm16;
    cudaGetSymbolAddress((void**)&z16,   g_z16);
    cudaGetSymbolAddress((void**)&att16, g_att16);
    cudaGetSymbolAddress((void**)&wq16,  g_wq16);
    cudaGetSymbolAddress((void**)&wm16,  g_wm16);

    cudaFuncSetAttribute(gemm_tc, cudaFuncAttributeMaxDynamicSharedMemorySize, G_SMEM);
    cudaFuncSetAttribute(attn_tc, cudaFuncAttributeMaxDynamicSharedMemorySize, AT_SMEM);

    const int total4 = N4_Z + N4_WQ + N4_WM;
    cvt_all<<<(total4 + 255) / 256, 256>>>(z, Wqkv, Wmsa);

    gemm_tc<<<dim3(RS / 128, MM / 128), 256, G_SMEM>>>(z16, wq16, bqkv,
                                                       out, RS, 1);
    attn_tc<<<dim3(NN / 128, HH, BB), 256, AT_SMEM>>>();
    gemm_tc<<<dim3(DD / 128, MM / 128), 256, G_SMEM>>>(att16, wm16, bmsa,
                                                       out, DD, 0);
}